// round 2
// baseline (speedup 1.0000x reference)
#include <cuda_runtime.h>

#define Bn  8
#define Cn  1024
#define HWn 4096
#define Kn  64

typedef unsigned long long ull;

// ---------------- device scratch (no allocations allowed) ----------------
__device__ float g_gT[Cn * Kn];        // normalized centroids, [c][k]
__device__ int   g_idx[Bn * HWn];      // argmax cluster per pixel
__device__ int   g_counts[Bn * Kn];
__device__ int   g_base[Bn * Kn];
__device__ int   g_cursor[Bn * Kn];
__device__ int   g_order[Bn * HWn];    // pixel ids grouped by cluster (per batch)
__device__ float g_cl[Bn * Kn * Cn];   // local centroids [b][k][c]
__device__ float g_wcl[Bn * Cn * Kn];  // W @ cl^T  [b][o][k]
__device__ float g_wmap[Bn * HWn];     // calibration weight per pixel

// ---------------- packed f32x2 helpers (Blackwell) ----------------
__device__ __forceinline__ ull pk2(float lo, float hi) {
    ull r; asm("mov.b64 %0, {%1, %2};" : "=l"(r) : "f"(lo), "f"(hi)); return r;
}
__device__ __forceinline__ ull ffma2(ull a, ull b, ull c) {
    ull d; asm("fma.rn.f32x2 %0, %1, %2, %3;" : "=l"(d) : "l"(a), "l"(b), "l"(c)); return d;
}
__device__ __forceinline__ float2 upk2(ull v) {
    float lo, hi; asm("mov.b64 {%0, %1}, %2;" : "=f"(lo), "=f"(hi) : "l"(v));
    return make_float2(lo, hi);
}

// ---------------- K0: normalize centroids (transposed store) + zero counts ----
__global__ void k_prep(const float* __restrict__ cent) {
    const int kk = blockIdx.x;
    const int t  = threadIdx.x;
    __shared__ float red[256];
    float s = 0.f;
    for (int c = t; c < Cn; c += 256) { float v = cent[kk * Cn + c]; s = fmaf(v, v, s); }
    red[t] = s; __syncthreads();
    for (int o = 128; o; o >>= 1) { if (t < o) red[t] += red[t + o]; __syncthreads(); }
    const float scale = 1.f / fmaxf(sqrtf(red[0]), 1e-12f);
    for (int c = t; c < Cn; c += 256) g_gT[c * Kn + kk] = cent[kk * Cn + c] * scale;
    if (blockIdx.x == 0 && t < 256) { g_counts[t] = 0; g_counts[256 + t] = 0; }
}

// ---------------- K1: nearest-centroid assignment (argmax of x . g_norm) ------
// argmax over k is invariant to the positive per-pixel 1/||x|| factor.
__global__ void k_assign(const float* __restrict__ x) {
    __shared__ float gs[32 * Kn];   // [cc][k]
    __shared__ int   hist[Kn];
    const int b = blockIdx.y;
    const int t = threadIdx.x;
    const int p = blockIdx.x * 128 + t;
    const float* xb = x + (size_t)b * Cn * HWn + p;

    float sim[Kn];
#pragma unroll
    for (int k = 0; k < Kn; k++) sim[k] = 0.f;

    for (int c0 = 0; c0 < Cn; c0 += 32) {
#pragma unroll
        for (int e = t; e < 32 * Kn; e += 128) gs[e] = g_gT[c0 * Kn + e];
        __syncthreads();
        float xv[32];
#pragma unroll
        for (int cc = 0; cc < 32; cc++) xv[cc] = xb[(size_t)(c0 + cc) * HWn];
#pragma unroll
        for (int cc = 0; cc < 32; cc++) {
#pragma unroll
            for (int k4 = 0; k4 < 16; k4++) {
                float4 g4 = *(const float4*)&gs[cc * Kn + k4 * 4];
                sim[k4 * 4 + 0] = fmaf(xv[cc], g4.x, sim[k4 * 4 + 0]);
                sim[k4 * 4 + 1] = fmaf(xv[cc], g4.y, sim[k4 * 4 + 1]);
                sim[k4 * 4 + 2] = fmaf(xv[cc], g4.z, sim[k4 * 4 + 2]);
                sim[k4 * 4 + 3] = fmaf(xv[cc], g4.w, sim[k4 * 4 + 3]);
            }
        }
        __syncthreads();
    }
    float best = sim[0]; int bi = 0;
#pragma unroll
    for (int k = 1; k < Kn; k++) if (sim[k] > best) { best = sim[k]; bi = k; }
    g_idx[b * HWn + p] = bi;

    if (t < Kn) hist[t] = 0;
    __syncthreads();
    atomicAdd(&hist[bi], 1);
    __syncthreads();
    if (t < Kn && hist[t]) atomicAdd(&g_counts[b * Kn + t], hist[t]);
}

// ---------------- K1b: per-batch exclusive prefix over cluster counts --------
__global__ void k_prefix() {
    const int b = blockIdx.x;
    if (threadIdx.x == 0) {
        int acc = 0;
        for (int k = 0; k < Kn; k++) {
            g_base[b * Kn + k]   = acc;
            g_cursor[b * Kn + k] = acc;
            acc += g_counts[b * Kn + k];
        }
    }
}

// ---------------- K1c: scatter pixel ids grouped by cluster ------------------
__global__ void k_scatter() {
    const int b = blockIdx.y;
    const int p = blockIdx.x * 256 + threadIdx.x;
    const int k = g_idx[b * HWn + p];
    const int pos = atomicAdd(&g_cursor[b * Kn + k], 1);
    g_order[b * HWn + pos] = p;
}

// ---------------- K2: local centroids via gather from SMEM-resident x rows ---
__global__ void k_cl(const float* __restrict__ x) {
    __shared__ float xr[2 * HWn];   // two channel rows, 32 KB
    const int b  = blockIdx.y;
    const int c0 = blockIdx.x * 2;
    const int t  = threadIdx.x;
    for (int e = t; e < 2 * HWn; e += 256)
        xr[e] = x[((size_t)b * Cn + c0 + (e >> 12)) * HWn + (e & (HWn - 1))];
    __syncthreads();
    const int warp = t >> 5, lane = t & 31;
    for (int k = warp; k < Kn; k += 8) {
        const int n   = g_counts[b * Kn + k];
        const int bas = g_base[b * Kn + k];
        float s0 = 0.f, s1 = 0.f;
        for (int i = lane; i < n; i += 32) {
            const int pix = g_order[b * HWn + bas + i];
            s0 += xr[pix];
            s1 += xr[HWn + pix];
        }
#pragma unroll
        for (int off = 16; off; off >>= 1) {
            s0 += __shfl_xor_sync(0xffffffffu, s0, off);
            s1 += __shfl_xor_sync(0xffffffffu, s1, off);
        }
        if (lane == 0) {
            const float inv = 1.f / (float)max(n, 1);
            g_cl[((size_t)b * Kn + k) * Cn + c0 + 0] = s0 * inv;
            g_cl[((size_t)b * Kn + k) * Cn + c0 + 1] = s1 * inv;
        }
    }
}

// ---------------- K3: Wcl[b,o,k] = sum_c W[o,c] * cl[b,k,c] ------------------
__global__ void k_wcl(const float* __restrict__ W) {
    __shared__ float wl[32 * 65];
    __shared__ float cls[64 * 64];
    const int b = blockIdx.y, o0 = blockIdx.x * 32, t = threadIdx.x;
    const int oL = t & 31, kset = (t >> 5) * 8;
    float acc[8];
#pragma unroll
    for (int i = 0; i < 8; i++) acc[i] = 0.f;
    for (int c0 = 0; c0 < Cn; c0 += 64) {
        for (int e = t; e < 2048; e += 256) {
            const int oi = e >> 6, ci = e & 63;
            wl[oi * 65 + ci] = W[(size_t)(o0 + oi) * Cn + c0 + ci];
        }
        for (int e = t; e < 4096; e += 256) {
            const int ki = e >> 6, ci = e & 63;
            cls[ki * 64 + ci] = g_cl[((size_t)b * Kn + ki) * Cn + c0 + ci];
        }
        __syncthreads();
        for (int ci = 0; ci < 64; ci++) {
            const float wv = wl[oL * 65 + ci];
#pragma unroll
            for (int kk = 0; kk < 8; kk++)
                acc[kk] = fmaf(wv, cls[(kset + kk) * 64 + ci], acc[kk]);
        }
        __syncthreads();
    }
#pragma unroll
    for (int kk = 0; kk < 8; kk++)
        g_wcl[((size_t)b * Cn + o0 + oL) * Kn + kset + kk] = acc[kk];
}

// ---------------- K4: calibration weight w_p = exp(-mean_c delta^2) ----------
__global__ void k_wmap(const float* __restrict__ x) {
    __shared__ float cls[64 * 65];  // [cc][k], padded
    const int b = blockIdx.y, t = threadIdx.x;
    const int p = blockIdx.x * 128 + t;
    const int myk = g_idx[b * HWn + p];
    const float* xb = x + (size_t)b * Cn * HWn + p;
    float acc = 0.f;
    for (int c0 = 0; c0 < Cn; c0 += 64) {
        for (int e = t; e < 4096; e += 128) {
            const int kk = e >> 6, cc = e & 63;
            cls[cc * 65 + kk] = g_cl[((size_t)b * Kn + kk) * Cn + c0 + cc];
        }
        __syncthreads();
#pragma unroll 8
        for (int cc = 0; cc < 64; cc++) {
            const float d = cls[cc * 65 + myk] - xb[(size_t)(c0 + cc) * HWn];
            acc = fmaf(d, d, acc);
        }
        __syncthreads();
    }
    g_wmap[b * HWn + p] = expf(-acc * (1.f / 1024.f));
}

// ---------------- K5: main GEMM (W @ x) with fused calibration epilogue ------
#define TO 128
#define TP 128
#define KCc 16
#define AST 132

__global__ __launch_bounds__(256) void k_gemm(const float* __restrict__ x,
                                              const float* __restrict__ W,
                                              const float* __restrict__ bias,
                                              float* __restrict__ out) {
    extern __shared__ float sm[];
    float* a_s = sm;                 // [KCc][AST]  (a_s[c][o], padded)
    float* b_s = sm + KCc * AST;     // [KCc][TP]
    const int b  = blockIdx.z;
    const int o0 = blockIdx.y * TO;
    const int p0 = blockIdx.x * TP;
    const int t  = threadIdx.x;
    const int tx = t & 15, ty = t >> 4;
    const float* xb = x + (size_t)b * Cn * HWn;

    ull acc[8][4];
#pragma unroll
    for (int i = 0; i < 8; i++)
#pragma unroll
        for (int j = 0; j < 4; j++) acc[i][j] = 0ull;

    for (int c0 = 0; c0 < Cn; c0 += KCc) {
#pragma unroll
        for (int e = t; e < TO * KCc; e += 256) {
            const int oi = e >> 4, ci = e & 15;
            a_s[ci * AST + oi] = W[(size_t)(o0 + oi) * Cn + c0 + ci];
        }
#pragma unroll
        for (int e = t; e < KCc * TP; e += 256) {
            const int ci = e >> 7, pj = e & 127;
            b_s[ci * TP + pj] = xb[(size_t)(c0 + ci) * HWn + p0 + pj];
        }
        __syncthreads();
#pragma unroll
        for (int kc = 0; kc < KCc; kc++) {
            const float4 a0 = *(const float4*)&a_s[kc * AST + ty * 8];
            const float4 a1 = *(const float4*)&a_s[kc * AST + ty * 8 + 4];
            const float4 b0 = *(const float4*)&b_s[kc * TP + tx * 8];
            const float4 b1 = *(const float4*)&b_s[kc * TP + tx * 8 + 4];
            ull bb[4] = { pk2(b0.x, b0.y), pk2(b0.z, b0.w),
                          pk2(b1.x, b1.y), pk2(b1.z, b1.w) };
            float av[8] = { a0.x, a0.y, a0.z, a0.w, a1.x, a1.y, a1.z, a1.w };
#pragma unroll
            for (int i = 0; i < 8; i++) {
                const ull aa = pk2(av[i], av[i]);
#pragma unroll
                for (int j = 0; j < 4; j++) acc[i][j] = ffma2(aa, bb[j], acc[i][j]);
            }
        }
        __syncthreads();
    }

    // epilogue: out = relu(g + w*(Wcl[idx] - g) + bias)
    float* wcl_s  = sm;              // [TO][Kn] = 8192 floats
    float* bias_s = sm + TO * Kn;
#pragma unroll
    for (int e = t; e < TO * Kn; e += 256)
        wcl_s[e] = g_wcl[(size_t)b * Cn * Kn + (size_t)o0 * Kn + e];
    if (t < TO) bias_s[t] = bias[o0 + t];
    __syncthreads();

    const int pb = p0 + tx * 8;
    float wp[8]; int kid[8];
#pragma unroll
    for (int j = 0; j < 8; j++) {
        wp[j]  = g_wmap[b * HWn + pb + j];
        kid[j] = g_idx[b * HWn + pb + j];
    }
#pragma unroll
    for (int i = 0; i < 8; i++) {
        const int o = o0 + ty * 8 + i;
        const float bi = bias_s[ty * 8 + i];
        const float* wrow = &wcl_s[(ty * 8 + i) * Kn];
        float r[8];
#pragma unroll
        for (int j = 0; j < 4; j++) {
            const float2 g = upk2(acc[i][j]);
            r[2 * j] = g.x; r[2 * j + 1] = g.y;
        }
#pragma unroll
        for (int j = 0; j < 8; j++) {
            const float v = r[j] + wp[j] * (wrow[kid[j]] - r[j]) + bi;
            r[j] = fmaxf(v, 0.f);
        }
        float* op = out + ((size_t)b * Cn + o) * HWn + pb;
        *(float4*)op       = make_float4(r[0], r[1], r[2], r[3]);
        *(float4*)(op + 4) = make_float4(r[4], r[5], r[6], r[7]);
    }
}

// ---------------- launch -----------------------------------------------------
extern "C" void kernel_launch(void* const* d_in, const int* in_sizes, int n_in,
                              void* d_out, int out_size) {
    const float* x    = (const float*)d_in[0];
    const float* cent = (const float*)d_in[1];
    const float* W    = (const float*)d_in[2];
    const float* bias = (const float*)d_in[3];
    float* out = (float*)d_out;

    k_prep   <<<Kn, 256>>>(cent);
    k_assign <<<dim3(HWn / 128, Bn), 128>>>(x);
    k_prefix <<<Bn, 32>>>();
    k_scatter<<<dim3(HWn / 256, Bn), 256>>>();
    k_cl     <<<dim3(Cn / 2, Bn), 256>>>(x);
    k_wcl    <<<dim3(Cn / 32, Bn), 256>>>(W);
    k_wmap   <<<dim3(HWn / 128, Bn), 128>>>(x);
    k_gemm   <<<dim3(HWn / TP, Cn / TO, Bn), 256, (TO * Kn + TO) * 4>>>(x, W, bias, out);
}

// round 7
// speedup vs baseline: 1.4819x; 1.4819x over previous
#include <cuda_runtime.h>
#include <cuda_bf16.h>
#include <cstdint>

#define Bn  8
#define Cn  1024
#define HWn 4096
#define Kn  64

// ---------------- device scratch (no allocations allowed) ----------------
__device__ float g_gT[Cn * Kn];        // normalized centroids, [c][k]
__device__ int   g_idx[Bn * HWn];      // argmax cluster per pixel
__device__ int   g_counts[Bn * Kn];
__device__ int   g_base[Bn * Kn];
__device__ int   g_cursor[Bn * Kn];
__device__ int   g_order[Bn * HWn];    // pixel ids grouped by cluster (per batch)
__device__ float g_cl[Bn * Kn * Cn];   // local centroids [b][k][c]
__device__ float g_wcl[Bn * Cn * Kn];  // W @ cl^T  [b][o][k]
__device__ float g_wmap[Bn * HWn];     // calibration weight per pixel

// bf16 hi/lo split operands for the tensor-core GEMM
__device__ __nv_bfloat16 g_wh[Cn * Cn];                       // W hi, [o][c]
__device__ __nv_bfloat16 g_wl[Cn * Cn];                       // W lo
__device__ __nv_bfloat16 g_xth[(size_t)Bn * HWn * Cn];        // x^T hi, [b][p][c]
__device__ __nv_bfloat16 g_xtl[(size_t)Bn * HWn * Cn];        // x^T lo

// ---------------- baseline-PTX helpers (compute_103-safe) ----------------
__device__ __forceinline__ uint32_t smem_u32(const void* p) {
    uint32_t a;
    asm("{ .reg .u64 t; cvta.to.shared.u64 t, %1; cvt.u32.u64 %0, t; }" : "=r"(a) : "l"(p));
    return a;
}
__device__ __forceinline__ void cpa16(uint32_t dst, const void* src) {
    asm volatile("cp.async.cg.shared.global [%0], [%1], 16;"
                 :: "r"(dst), "l"(__cvta_generic_to_global(src)) : "memory");
}
#define CP_COMMIT() asm volatile("cp.async.commit_group;" ::: "memory")
#define CP_WAIT1()  asm volatile("cp.async.wait_group 1;" ::: "memory")
#define CP_WAIT0()  asm volatile("cp.async.wait_group 0;" ::: "memory")

__device__ __forceinline__ void ldsm_x4(uint32_t* r, uint32_t addr) {
    asm volatile("ldmatrix.sync.aligned.m8n8.x4.shared.b16 {%0,%1,%2,%3}, [%4];"
                 : "=r"(r[0]), "=r"(r[1]), "=r"(r[2]), "=r"(r[3]) : "r"(addr));
}
__device__ __forceinline__ void mma16816(float* d, const uint32_t* a, const uint32_t* b) {
    asm volatile("mma.sync.aligned.m16n8k16.row.col.f32.bf16.bf16.f32 "
                 "{%0,%1,%2,%3}, {%4,%5,%6,%7}, {%8,%9}, {%0,%1,%2,%3};"
                 : "+f"(d[0]), "+f"(d[1]), "+f"(d[2]), "+f"(d[3])
                 : "r"(a[0]), "r"(a[1]), "r"(a[2]), "r"(a[3]), "r"(b[0]), "r"(b[1]));
}

// ---------------- K0: normalize centroids (transposed store) + zero counts ----
__global__ void k_prep(const float* __restrict__ cent) {
    const int kk = blockIdx.x;
    const int t  = threadIdx.x;
    __shared__ float red[256];
    float s = 0.f;
    for (int c = t; c < Cn; c += 256) { float v = cent[kk * Cn + c]; s = fmaf(v, v, s); }
    red[t] = s; __syncthreads();
    for (int o = 128; o; o >>= 1) { if (t < o) red[t] += red[t + o]; __syncthreads(); }
    const float scale = 1.f / fmaxf(sqrtf(red[0]), 1e-12f);
    for (int c = t; c < Cn; c += 256) g_gT[c * Kn + kk] = cent[kk * Cn + c] * scale;
    if (blockIdx.x == 0 && t < 256) { g_counts[t] = 0; g_counts[256 + t] = 0; }
}

// ---------------- K1: nearest-centroid assignment ----------------------------
__global__ void k_assign(const float* __restrict__ x) {
    __shared__ float gs[32 * Kn];
    __shared__ int   hist[Kn];
    const int b = blockIdx.y;
    const int t = threadIdx.x;
    const int p = blockIdx.x * 128 + t;
    const float* xb = x + (size_t)b * Cn * HWn + p;

    float sim[Kn];
#pragma unroll
    for (int k = 0; k < Kn; k++) sim[k] = 0.f;

    for (int c0 = 0; c0 < Cn; c0 += 32) {
#pragma unroll
        for (int e = t; e < 32 * Kn; e += 128) gs[e] = g_gT[c0 * Kn + e];
        __syncthreads();
        float xv[32];
#pragma unroll
        for (int cc = 0; cc < 32; cc++) xv[cc] = xb[(size_t)(c0 + cc) * HWn];
#pragma unroll
        for (int cc = 0; cc < 32; cc++) {
#pragma unroll
            for (int k4 = 0; k4 < 16; k4++) {
                float4 g4 = *(const float4*)&gs[cc * Kn + k4 * 4];
                sim[k4 * 4 + 0] = fmaf(xv[cc], g4.x, sim[k4 * 4 + 0]);
                sim[k4 * 4 + 1] = fmaf(xv[cc], g4.y, sim[k4 * 4 + 1]);
                sim[k4 * 4 + 2] = fmaf(xv[cc], g4.z, sim[k4 * 4 + 2]);
                sim[k4 * 4 + 3] = fmaf(xv[cc], g4.w, sim[k4 * 4 + 3]);
            }
        }
        __syncthreads();
    }
    float best = sim[0]; int bi = 0;
#pragma unroll
    for (int k = 1; k < Kn; k++) if (sim[k] > best) { best = sim[k]; bi = k; }
    g_idx[b * HWn + p] = bi;

    if (t < Kn) hist[t] = 0;
    __syncthreads();
    atomicAdd(&hist[bi], 1);
    __syncthreads();
    if (t < Kn && hist[t]) atomicAdd(&g_counts[b * Kn + t], hist[t]);
}

// ---------------- K1b: per-batch exclusive prefix -----------------------------
__global__ void k_prefix() {
    const int b = blockIdx.x;
    if (threadIdx.x == 0) {
        int acc = 0;
        for (int k = 0; k < Kn; k++) {
            g_base[b * Kn + k]   = acc;
            g_cursor[b * Kn + k] = acc;
            acc += g_counts[b * Kn + k];
        }
    }
}

// ---------------- K1c: scatter pixel ids grouped by cluster ------------------
__global__ void k_scatter() {
    const int b = blockIdx.y;
    const int p = blockIdx.x * 256 + threadIdx.x;
    const int k = g_idx[b * HWn + p];
    const int pos = atomicAdd(&g_cursor[b * Kn + k], 1);
    g_order[b * HWn + pos] = p;
}

// ---------------- K2: local centroids via gather ------------------------------
__global__ void k_cl(const float* __restrict__ x) {
    __shared__ float xr[2 * HWn];
    const int b  = blockIdx.y;
    const int c0 = blockIdx.x * 2;
    const int t  = threadIdx.x;
    for (int e = t; e < 2 * HWn; e += 256)
        xr[e] = x[((size_t)b * Cn + c0 + (e >> 12)) * HWn + (e & (HWn - 1))];
    __syncthreads();
    const int warp = t >> 5, lane = t & 31;
    for (int k = warp; k < Kn; k += 8) {
        const int n   = g_counts[b * Kn + k];
        const int bas = g_base[b * Kn + k];
        float s0 = 0.f, s1 = 0.f;
        for (int i = lane; i < n; i += 32) {
            const int pix = g_order[b * HWn + bas + i];
            s0 += xr[pix];
            s1 += xr[HWn + pix];
        }
#pragma unroll
        for (int off = 16; off; off >>= 1) {
            s0 += __shfl_xor_sync(0xffffffffu, s0, off);
            s1 += __shfl_xor_sync(0xffffffffu, s1, off);
        }
        if (lane == 0) {
            const float inv = 1.f / (float)max(n, 1);
            g_cl[((size_t)b * Kn + k) * Cn + c0 + 0] = s0 * inv;
            g_cl[((size_t)b * Kn + k) * Cn + c0 + 1] = s1 * inv;
        }
    }
}

// ---------------- K3: Wcl[b,o,k] = sum_c W[o,c] * cl[b,k,c] ------------------
__global__ void k_wcl(const float* __restrict__ W) {
    __shared__ float wl[32 * 65];
    __shared__ float cls[64 * 64];
    const int b = blockIdx.y, o0 = blockIdx.x * 32, t = threadIdx.x;
    const int oL = t & 31, kset = (t >> 5) * 8;
    float acc[8];
#pragma unroll
    for (int i = 0; i < 8; i++) acc[i] = 0.f;
    for (int c0 = 0; c0 < Cn; c0 += 64) {
        for (int e = t; e < 2048; e += 256) {
            const int oi = e >> 6, ci = e & 63;
            wl[oi * 65 + ci] = W[(size_t)(o0 + oi) * Cn + c0 + ci];
        }
        for (int e = t; e < 4096; e += 256) {
            const int ki = e >> 6, ci = e & 63;
            cls[ki * 64 + ci] = g_cl[((size_t)b * Kn + ki) * Cn + c0 + ci];
        }
        __syncthreads();
        for (int ci = 0; ci < 64; ci++) {
            const float wv = wl[oL * 65 + ci];
#pragma unroll
            for (int kk = 0; kk < 8; kk++)
                acc[kk] = fmaf(wv, cls[(kset + kk) * 64 + ci], acc[kk]);
        }
        __syncthreads();
    }
#pragma unroll
    for (int kk = 0; kk < 8; kk++)
        g_wcl[((size_t)b * Cn + o0 + oL) * Kn + kset + kk] = acc[kk];
}

// ---------------- K4: calibration weight map ----------------------------------
__global__ void k_wmap(const float* __restrict__ x) {
    __shared__ float cls[64 * 65];
    const int b = blockIdx.y, t = threadIdx.x;
    const int p = blockIdx.x * 128 + t;
    const int myk = g_idx[b * HWn + p];
    const float* xb = x + (size_t)b * Cn * HWn + p;
    float acc = 0.f;
    for (int c0 = 0; c0 < Cn; c0 += 64) {
        for (int e = t; e < 4096; e += 128) {
            const int kk = e >> 6, cc = e & 63;
            cls[cc * 65 + kk] = g_cl[((size_t)b * Kn + kk) * Cn + c0 + cc];
        }
        __syncthreads();
#pragma unroll 8
        for (int cc = 0; cc < 64; cc++) {
            const float d = cls[cc * 65 + myk] - xb[(size_t)(c0 + cc) * HWn];
            acc = fmaf(d, d, acc);
        }
        __syncthreads();
    }
    g_wmap[b * HWn + p] = expf(-acc * (1.f / 1024.f));
}

// ---------------- K5a: split W into bf16 hi/lo --------------------------------
__global__ void k_splitW(const float* __restrict__ W) {
    const int i = (blockIdx.x * 256 + threadIdx.x) * 2;
    const float2 v = *(const float2*)(W + i);
    __nv_bfloat16 h0 = __float2bfloat16(v.x), h1 = __float2bfloat16(v.y);
    __nv_bfloat162 hh; hh.x = h0; hh.y = h1;
    __nv_bfloat162 ll;
    ll.x = __float2bfloat16(v.x - __bfloat162float(h0));
    ll.y = __float2bfloat16(v.y - __bfloat162float(h1));
    *(__nv_bfloat162*)(g_wh + i) = hh;
    *(__nv_bfloat162*)(g_wl + i) = ll;
}

// ---------------- K5b: transpose + split x into bf16 hi/lo [b][p][c] ----------
__global__ void k_splitX(const float* __restrict__ x) {
    __shared__ float tile[32][65];   // [pj][ci]
    const int b = blockIdx.z, p0 = blockIdx.x * 32, c0 = blockIdx.y * 64;
    const int t = threadIdx.x;
    for (int e = t; e < 2048; e += 256) {
        const int ci = e >> 5, pj = e & 31;
        tile[pj][ci] = x[((size_t)b * Cn + c0 + ci) * HWn + p0 + pj];
    }
    __syncthreads();
    for (int e = t; e < 1024; e += 256) {
        const int pj = e >> 5, c2 = (e & 31) * 2;
        const float v0 = tile[pj][c2], v1 = tile[pj][c2 + 1];
        __nv_bfloat16 h0 = __float2bfloat16(v0), h1 = __float2bfloat16(v1);
        __nv_bfloat162 hh; hh.x = h0; hh.y = h1;
        __nv_bfloat162 ll;
        ll.x = __float2bfloat16(v0 - __bfloat162float(h0));
        ll.y = __float2bfloat16(v1 - __bfloat162float(h1));
        const size_t dst = ((size_t)b * HWn + p0 + pj) * Cn + c0 + c2;
        *(__nv_bfloat162*)(g_xth + dst) = hh;
        *(__nv_bfloat162*)(g_xtl + dst) = ll;
    }
}

// ---------------- K6: HMMA (mma.sync bf16 split) GEMM + fused epilogue --------
// D[128 o, 128 p] = (Wh+Wl)[o,c]*(Xh+Xl)[p,c] over c (drop lo*lo term).
#define PT      40                   // SMEM row pitch in bf16 elems (80 B, conflict-free)
#define TILE_B  (128 * PT * 2)       // 10240 B per operand tile
#define STAGE_B (4 * TILE_B)         // Ah, Al, Bh, Bl
#define NCH     (Cn / 32)            // 32 k-chunks of 32
#define GEMM_SMEM (2 * STAGE_B)      // 81920 B

__device__ __forceinline__ void load_chunk(uint32_t base, int b, int o0, int p0,
                                           int k0, int t) {
#pragma unroll
    for (int e = t; e < 512; e += 256) {
        const int row = e >> 2, g = e & 3;
        const uint32_t d = base + row * (PT * 2) + g * 16;
        const size_t sA = (size_t)(o0 + row) * Cn + k0 + g * 8;
        cpa16(d,              g_wh + sA);
        cpa16(d + TILE_B,     g_wl + sA);
        const size_t sB = ((size_t)b * HWn + p0 + row) * Cn + k0 + g * 8;
        cpa16(d + 2 * TILE_B, g_xth + sB);
        cpa16(d + 3 * TILE_B, g_xtl + sB);
    }
}

__global__ __launch_bounds__(256, 1) void k_gemm_mma(const float* __restrict__ bias,
                                                     float* __restrict__ out) {
    extern __shared__ __align__(128) char smem[];
    const uint32_t sbase = smem_u32(smem);
    const int t = threadIdx.x;
    const int wid = t >> 5, lane = t & 31;
    const int wm = wid >> 2, wn = wid & 3;      // warp tile: 64(o) x 32(p)
    const int b  = blockIdx.z;
    const int o0 = blockIdx.y * 128;
    const int p0 = blockIdx.x * 128;

    // per-lane ldmatrix base offsets (bytes within a tile)
    const int alr = lane & 15, alc = (lane >> 4) << 3;
    const uint32_t a_lane = (uint32_t)(((wm * 64 + alr) * PT + alc) * 2);
    const int brow = ((lane >> 4) << 3) + (lane & 7);
    const int bkc  = ((lane >> 3) & 1) << 3;
    const uint32_t b_lane = (uint32_t)(((wn * 32 + brow) * PT + bkc) * 2);

    float acc[4][4][4];
#pragma unroll
    for (int i = 0; i < 4; i++)
#pragma unroll
        for (int j = 0; j < 4; j++)
#pragma unroll
            for (int q = 0; q < 4; q++) acc[i][j][q] = 0.f;

    load_chunk(sbase, b, o0, p0, 0, t);  CP_COMMIT();
    load_chunk(sbase + STAGE_B, b, o0, p0, 32, t);  CP_COMMIT();

    for (int c = 0; c < NCH; c++) {
        CP_WAIT1();
        __syncthreads();
        const uint32_t st = sbase + (c & 1) * STAGE_B;
#pragma unroll
        for (int ks = 0; ks < 2; ks++) {
            uint32_t bh[8], bl[8];
            ldsm_x4(bh + 0, st + 2 * TILE_B + b_lane + ks * 32);
            ldsm_x4(bh + 4, st + 2 * TILE_B + b_lane + 16 * PT * 2 + ks * 32);
            ldsm_x4(bl + 0, st + 3 * TILE_B + b_lane + ks * 32);
            ldsm_x4(bl + 4, st + 3 * TILE_B + b_lane + 16 * PT * 2 + ks * 32);
#pragma unroll
            for (int mf = 0; mf < 4; mf++) {
                uint32_t ah[4], al[4];
                ldsm_x4(ah, st + a_lane + mf * 16 * PT * 2 + ks * 32);
                ldsm_x4(al, st + TILE_B + a_lane + mf * 16 * PT * 2 + ks * 32);
#pragma unroll
                for (int nf = 0; nf < 4; nf++) {
                    mma16816(acc[mf][nf], ah, &bh[nf * 2]);
                    mma16816(acc[mf][nf], ah, &bl[nf * 2]);
                    mma16816(acc[mf][nf], al, &bh[nf * 2]);
                }
            }
        }
        __syncthreads();
        if (c + 2 < NCH)
            load_chunk(sbase + (c & 1) * STAGE_B, b, o0, p0, (c + 2) * 32, t);
        CP_COMMIT();
    }
    CP_WAIT0();
    __syncthreads();

    // ---------------- epilogue: side tables in SMEM, fused calibration --------
    float* wcl_s  = (float*)smem;            // [128][65]
    float* bias_s = wcl_s + 128 * 65;
    float* wp_s   = bias_s + 128;
    int*   kid_s  = (int*)(wp_s + 128);
    for (int e = t; e < 128 * Kn; e += 256) {
        const int oi = e >> 6, k = e & 63;
        wcl_s[oi * 65 + k] = g_wcl[(size_t)b * Cn * Kn + (size_t)(o0 + oi) * Kn + k];
    }
    if (t < 128) {
        bias_s[t] = bias[o0 + t];
        wp_s[t]   = g_wmap[b * HWn + p0 + t];
        kid_s[t]  = g_idx[b * HWn + p0 + t];
    }
    __syncthreads();

    const int ql = lane >> 2, rl = (lane & 3) * 2;
#pragma unroll
    for (int mf = 0; mf < 4; mf++) {
        const int r0 = wm * 64 + mf * 16 + ql;
        const float bi0 = bias_s[r0], bi1 = bias_s[r0 + 8];
        const float* w0 = &wcl_s[r0 * 65];
        const float* w1 = w0 + 8 * 65;
        float* op0 = out + ((size_t)b * Cn + o0 + r0) * HWn + p0;
        float* op1 = op0 + (size_t)8 * HWn;
#pragma unroll
        for (int nf = 0; nf < 4; nf++) {
            const int cc = wn * 32 + nf * 8 + rl;
            const float wpa = wp_s[cc], wpb = wp_s[cc + 1];
            const int   ka  = kid_s[cc], kb = kid_s[cc + 1];
            const float* d = acc[mf][nf];
            float2 v0, v1;
            v0.x = fmaxf(d[0] + wpa * (w0[ka] - d[0]) + bi0, 0.f);
            v0.y = fmaxf(d[1] + wpb * (w0[kb] - d[1]) + bi0, 0.f);
            v1.x = fmaxf(d[2] + wpa * (w1[ka] - d[2]) + bi1, 0.f);
            v1.y = fmaxf(d[3] + wpb * (w1[kb] - d[3]) + bi1, 0.f);
            *(float2*)(op0 + cc) = v0;
            *(float2*)(op1 + cc) = v1;
        }
    }
}

// ---------------- launch -----------------------------------------------------
extern "C" void kernel_launch(void* const* d_in, const int* in_sizes, int n_in,
                              void* d_out, int out_size) {
    const float* x    = (const float*)d_in[0];
    const float* cent = (const float*)d_in[1];
    const float* W    = (const float*)d_in[2];
    const float* bias = (const float*)d_in[3];
    float* out = (float*)d_out;

    cudaFuncSetAttribute(k_gemm_mma, cudaFuncAttributeMaxDynamicSharedMemorySize, GEMM_SMEM);

    k_splitW <<<Cn * Cn / 512, 256>>>(W);
    k_splitX <<<dim3(HWn / 32, Cn / 64, Bn), 256>>>(x);
    k_prep   <<<Kn, 256>>>(cent);
    k_assign <<<dim3(HWn / 128, Bn), 128>>>(x);
    k_prefix <<<Bn, 32>>>();
    k_scatter<<<dim3(HWn / 256, Bn), 256>>>();
    k_cl     <<<dim3(Cn / 2, Bn), 256>>>(x);
    k_wcl    <<<dim3(Cn / 32, Bn), 256>>>(W);
    k_wmap   <<<dim3(HWn / 128, Bn), 128>>>(x);
    k_gemm_mma<<<dim3(HWn / 128, Cn / 128, Bn), 256, GEMM_SMEM>>>(bias, out);
}

// round 9
// speedup vs baseline: 1.8060x; 1.2187x over previous
#include <cuda_runtime.h>
#include <cuda_bf16.h>
#include <cstdint>

#define Bn  8
#define Cn  1024
#define HWn 4096
#define Kn  64

// ---------------- device scratch (no allocations allowed) ----------------
__device__ int   g_idx[Bn * HWn];      // argmax cluster per pixel
__device__ int   g_counts[Bn * Kn];
__device__ int   g_base[Bn * Kn];
__device__ int   g_cursor[Bn * Kn];
__device__ int   g_order[Bn * HWn];    // pixel ids grouped by cluster (per batch)
__device__ float g_cl[Bn * Kn * Cn];   // local centroids [b][k][c]
__device__ float g_wcl[Bn * Cn * Kn];  // W @ cl^T  [b][o][k]
__device__ float g_wmap[Bn * HWn];     // calibration weight per pixel
__device__ float g_xsq[Bn * HWn];      // ||x_p||^2
__device__ float g_clsq[Bn * Kn];      // ||cl_k||^2

// bf16 hi/lo split operands
__device__ __nv_bfloat16 g_wh[Cn * Cn];                       // W hi, [o][c]
__device__ __nv_bfloat16 g_wl[Cn * Cn];                       // W lo
__device__ __nv_bfloat16 g_xth[(size_t)Bn * HWn * Cn];        // x^T hi, [b][p][c]
__device__ __nv_bfloat16 g_xtl[(size_t)Bn * HWn * Cn];        // x^T lo
__device__ __nv_bfloat16 g_cnh[Kn * Cn];                      // normalized centroids hi [k][c]
__device__ __nv_bfloat16 g_cnl[Kn * Cn];                      // normalized centroids lo
__device__ __nv_bfloat16 g_clh[Bn * Kn * Cn];                 // local centroids hi [b][k][c]
__device__ __nv_bfloat16 g_cll[Bn * Kn * Cn];                 // local centroids lo

// ---------------- baseline-PTX helpers (compute_103-safe) ----------------
__device__ __forceinline__ uint32_t smem_u32(const void* p) {
    uint32_t a;
    asm("{ .reg .u64 t; cvta.to.shared.u64 t, %1; cvt.u32.u64 %0, t; }" : "=r"(a) : "l"(p));
    return a;
}
__device__ __forceinline__ void cpa16(uint32_t dst, const void* src) {
    asm volatile("cp.async.cg.shared.global [%0], [%1], 16;"
                 :: "r"(dst), "l"(__cvta_generic_to_global(src)) : "memory");
}
#define CP_COMMIT() asm volatile("cp.async.commit_group;" ::: "memory")
#define CP_WAIT1()  asm volatile("cp.async.wait_group 1;" ::: "memory")
#define CP_WAIT0()  asm volatile("cp.async.wait_group 0;" ::: "memory")

__device__ __forceinline__ void ldsm_x4(uint32_t* r, uint32_t addr) {
    asm volatile("ldmatrix.sync.aligned.m8n8.x4.shared.b16 {%0,%1,%2,%3}, [%4];"
                 : "=r"(r[0]), "=r"(r[1]), "=r"(r[2]), "=r"(r[3]) : "r"(addr));
}
__device__ __forceinline__ void mma16816(float* d, const uint32_t* a, const uint32_t* b) {
    asm volatile("mma.sync.aligned.m16n8k16.row.col.f32.bf16.bf16.f32 "
                 "{%0,%1,%2,%3}, {%4,%5,%6,%7}, {%8,%9}, {%0,%1,%2,%3};"
                 : "+f"(d[0]), "+f"(d[1]), "+f"(d[2]), "+f"(d[3])
                 : "r"(a[0]), "r"(a[1]), "r"(a[2]), "r"(a[3]), "r"(b[0]), "r"(b[1]));
}

// ---------------- K0: normalize centroids -> bf16 hi/lo [k][c]; zero counts ---
__global__ void k_prep(const float* __restrict__ cent) {
    const int kk = blockIdx.x;
    const int t  = threadIdx.x;
    __shared__ float red[256];
    float s = 0.f;
    for (int c = t; c < Cn; c += 256) { float v = cent[kk * Cn + c]; s = fmaf(v, v, s); }
    red[t] = s; __syncthreads();
    for (int o = 128; o; o >>= 1) { if (t < o) red[t] += red[t + o]; __syncthreads(); }
    const float scale = 1.f / fmaxf(sqrtf(red[0]), 1e-12f);
    for (int c = t; c < Cn; c += 256) {
        const float v = cent[kk * Cn + c] * scale;
        const __nv_bfloat16 h = __float2bfloat16(v);
        g_cnh[kk * Cn + c] = h;
        g_cnl[kk * Cn + c] = __float2bfloat16(v - __bfloat162float(h));
    }
    if (blockIdx.x == 0 && t < 256) { g_counts[t] = 0; g_counts[256 + t] = 0; }
}

// ---------------- score kernels: S[128p x 64k] = A . B^T via split MMA --------
#define PT      40                   // SMEM pitch in bf16 elems (80 B)
#define SC_AT   (128 * PT * 2)       // 10240 B per A tile
#define SC_BT   (64 * PT * 2)        // 5120 B per B tile
#define SC_STAGE (2 * SC_AT + 2 * SC_BT)   // 30720
#define SC_SMEM  (2 * SC_STAGE)            // 61440
#define SC_NCH   (Cn / 32)

__device__ __forceinline__ void sc_load(uint32_t base,
                                        const __nv_bfloat16* Ah, const __nv_bfloat16* Al,
                                        const __nv_bfloat16* Bh, const __nv_bfloat16* Bl,
                                        int k0, int t) {
#pragma unroll
    for (int e = t; e < 512; e += 256) {
        const int row = e >> 2, g = e & 3;
        const uint32_t d = base + row * (PT * 2) + g * 16;
        const size_t s = (size_t)row * Cn + k0 + g * 8;
        cpa16(d,         Ah + s);
        cpa16(d + SC_AT, Al + s);
    }
    {
        const int row = t >> 2, g = t & 3;
        const uint32_t d = base + 2 * SC_AT + row * (PT * 2) + g * 16;
        const size_t s = (size_t)row * Cn + k0 + g * 8;
        cpa16(d,         Bh + s);
        cpa16(d + SC_BT, Bl + s);
    }
}

// computes S into sS[128][66] (fp32), caller supplies pointers
__device__ __forceinline__ void sc_compute(char* smem, float* sS,
                                           const __nv_bfloat16* Ah, const __nv_bfloat16* Al,
                                           const __nv_bfloat16* Bh, const __nv_bfloat16* Bl,
                                           int t) {
    const uint32_t sbase = smem_u32(smem);
    const int wid = t >> 5, lane = t & 31;
    const int wm = wid >> 1, wn = wid & 1;       // warp tile 32p x 32k
    const int alr = lane & 15, alc = (lane >> 4) << 3;
    const uint32_t a_lane = (uint32_t)(((wm * 32 + alr) * PT + alc) * 2);
    const int brow = ((lane >> 4) << 3) + (lane & 7);
    const int bkc  = ((lane >> 3) & 1) << 3;
    const uint32_t b_lane = (uint32_t)(((wn * 32 + brow) * PT + bkc) * 2);

    float acc[2][4][4];
#pragma unroll
    for (int i = 0; i < 2; i++)
#pragma unroll
        for (int j = 0; j < 4; j++)
#pragma unroll
            for (int q = 0; q < 4; q++) acc[i][j][q] = 0.f;

    sc_load(sbase, Ah, Al, Bh, Bl, 0, t);  CP_COMMIT();
    sc_load(sbase + SC_STAGE, Ah, Al, Bh, Bl, 32, t);  CP_COMMIT();

    for (int c = 0; c < SC_NCH; c++) {
        CP_WAIT1();
        __syncthreads();
        const uint32_t st = sbase + (c & 1) * SC_STAGE;
#pragma unroll
        for (int ks = 0; ks < 2; ks++) {
            uint32_t bh[8], bl[8];
            ldsm_x4(bh + 0, st + 2 * SC_AT + b_lane + ks * 32);
            ldsm_x4(bh + 4, st + 2 * SC_AT + b_lane + 16 * PT * 2 + ks * 32);
            ldsm_x4(bl + 0, st + 2 * SC_AT + SC_BT + b_lane + ks * 32);
            ldsm_x4(bl + 4, st + 2 * SC_AT + SC_BT + b_lane + 16 * PT * 2 + ks * 32);
#pragma unroll
            for (int mf = 0; mf < 2; mf++) {
                uint32_t ah[4], al[4];
                ldsm_x4(ah, st + a_lane + mf * 16 * PT * 2 + ks * 32);
                ldsm_x4(al, st + SC_AT + a_lane + mf * 16 * PT * 2 + ks * 32);
#pragma unroll
                for (int nf = 0; nf < 4; nf++) {
                    mma16816(acc[mf][nf], ah, &bh[nf * 2]);
                    mma16816(acc[mf][nf], ah, &bl[nf * 2]);
                    mma16816(acc[mf][nf], al, &bh[nf * 2]);
                }
            }
        }
        __syncthreads();
        if (c + 2 < SC_NCH)
            sc_load(sbase + (c & 1) * SC_STAGE, Ah, Al, Bh, Bl, (c + 2) * 32, t);
        CP_COMMIT();
    }
    CP_WAIT0();
    __syncthreads();

    const int ql = lane >> 2, rl = (lane & 3) * 2;
#pragma unroll
    for (int mf = 0; mf < 2; mf++) {
        const int row = wm * 32 + mf * 16 + ql;
#pragma unroll
        for (int nf = 0; nf < 4; nf++) {
            const int col = wn * 32 + nf * 8 + rl;
            const float* d = acc[mf][nf];
            sS[row * 66 + col]           = d[0];
            sS[row * 66 + col + 1]       = d[1];
            sS[(row + 8) * 66 + col]     = d[2];
            sS[(row + 8) * 66 + col + 1] = d[3];
        }
    }
    __syncthreads();
}

// K1: nearest-centroid assignment via MMA scores
__global__ __launch_bounds__(256, 2) void k_score_argmax() {
    extern __shared__ __align__(128) char smem[];
    float* sS = (float*)smem;
    int* hist = (int*)(smem + 128 * 66 * 4);
    const int t = threadIdx.x;
    const int b = blockIdx.y;
    const int p0 = blockIdx.x * 128;
    const __nv_bfloat16* Ah = g_xth + ((size_t)b * HWn + p0) * Cn;
    const __nv_bfloat16* Al = g_xtl + ((size_t)b * HWn + p0) * Cn;

    sc_compute(smem, sS, Ah, Al, g_cnh, g_cnl, t);

    if (t < Kn) hist[t] = 0;
    __syncthreads();
    if (t < 128) {
        const float* row = sS + t * 66;
        float best = row[0]; int bi = 0;
#pragma unroll
        for (int k = 1; k < Kn; k++) { const float v = row[k]; if (v > best) { best = v; bi = k; } }
        g_idx[b * HWn + p0 + t] = bi;
        atomicAdd(&hist[bi], 1);
    }
    __syncthreads();
    if (t < Kn && hist[t]) atomicAdd(&g_counts[b * Kn + t], hist[t]);
}

// K4: calibration weight map via MMA scores against local centroids
__global__ __launch_bounds__(256, 2) void k_score_wmap() {
    extern __shared__ __align__(128) char smem[];
    float* sS = (float*)smem;
    float* clsq_s = (float*)(smem + 128 * 66 * 4);
    const int t = threadIdx.x;
    const int b = blockIdx.y;
    const int p0 = blockIdx.x * 128;
    const __nv_bfloat16* Ah = g_xth + ((size_t)b * HWn + p0) * Cn;
    const __nv_bfloat16* Al = g_xtl + ((size_t)b * HWn + p0) * Cn;
    const __nv_bfloat16* Bh = g_clh + (size_t)b * Kn * Cn;
    const __nv_bfloat16* Bl = g_cll + (size_t)b * Kn * Cn;

    sc_compute(smem, sS, Ah, Al, Bh, Bl, t);

    if (t < Kn) clsq_s[t] = g_clsq[b * Kn + t];
    __syncthreads();
    if (t < 128) {
        const int p = p0 + t;
        const int k = g_idx[b * HWn + p];
        const float D = sS[t * 66 + k];
        const float q = g_xsq[b * HWn + p] - 2.f * D + clsq_s[k];
        g_wmap[b * HWn + p] = expf(-q * (1.f / 1024.f));
    }
}

// ---------------- K1b: per-batch exclusive prefix -----------------------------
__global__ void k_prefix() {
    const int b = blockIdx.x;
    if (threadIdx.x == 0) {
        int acc = 0;
        for (int k = 0; k < Kn; k++) {
            g_base[b * Kn + k]   = acc;
            g_cursor[b * Kn + k] = acc;
            acc += g_counts[b * Kn + k];
        }
    }
}

// ---------------- K1c: scatter pixel ids grouped by cluster ------------------
__global__ void k_scatter() {
    const int b = blockIdx.y;
    const int p = blockIdx.x * 256 + threadIdx.x;
    const int k = g_idx[b * HWn + p];
    const int pos = atomicAdd(&g_cursor[b * Kn + k], 1);
    g_order[b * HWn + pos] = p;
}

// ---------------- K2: local centroids via gather ------------------------------
__global__ void k_cl(const float* __restrict__ x) {
    __shared__ float xr[2 * HWn];
    const int b  = blockIdx.y;
    const int c0 = blockIdx.x * 2;
    const int t  = threadIdx.x;
    for (int e = t; e < 2 * HWn; e += 256)
        xr[e] = x[((size_t)b * Cn + c0 + (e >> 12)) * HWn + (e & (HWn - 1))];
    __syncthreads();
    const int warp = t >> 5, lane = t & 31;
    for (int k = warp; k < Kn; k += 8) {
        const int n   = g_counts[b * Kn + k];
        const int bas = g_base[b * Kn + k];
        float s0 = 0.f, s1 = 0.f;
        for (int i = lane; i < n; i += 32) {
            const int pix = g_order[b * HWn + bas + i];
            s0 += xr[pix];
            s1 += xr[HWn + pix];
        }
#pragma unroll
        for (int off = 16; off; off >>= 1) {
            s0 += __shfl_xor_sync(0xffffffffu, s0, off);
            s1 += __shfl_xor_sync(0xffffffffu, s1, off);
        }
        if (lane == 0) {
            const float inv = 1.f / (float)max(n, 1);
            g_cl[((size_t)b * Kn + k) * Cn + c0 + 0] = s0 * inv;
            g_cl[((size_t)b * Kn + k) * Cn + c0 + 1] = s1 * inv;
        }
    }
}

// ---------------- K2b: split local centroids to bf16 hi/lo + ||cl||^2 --------
__global__ void k_clsplit() {
    const int bk = blockIdx.x;           // b*Kn + k
    const int t  = threadIdx.x;
    __shared__ float red[256];
    float s = 0.f;
    for (int c = t; c < Cn; c += 256) {
        const float v = g_cl[(size_t)bk * Cn + c];
        const __nv_bfloat16 h = __float2bfloat16(v);
        g_clh[(size_t)bk * Cn + c] = h;
        g_cll[(size_t)bk * Cn + c] = __float2bfloat16(v - __bfloat162float(h));
        s = fmaf(v, v, s);
    }
    red[t] = s; __syncthreads();
    for (int o = 128; o; o >>= 1) { if (t < o) red[t] += red[t + o]; __syncthreads(); }
    if (t == 0) g_clsq[bk] = red[0];
}

// ---------------- K3: Wcl[b,o,k] = sum_c W[o,c] * cl[b,k,c] ------------------
__global__ void k_wcl(const float* __restrict__ W) {
    __shared__ float wl[32 * 65];
    __shared__ float cls[64 * 64];
    const int b = blockIdx.y, o0 = blockIdx.x * 32, t = threadIdx.x;
    const int oL = t & 31, kset = (t >> 5) * 8;
    float acc[8];
#pragma unroll
    for (int i = 0; i < 8; i++) acc[i] = 0.f;
    for (int c0 = 0; c0 < Cn; c0 += 64) {
        for (int e = t; e < 2048; e += 256) {
            const int oi = e >> 6, ci = e & 63;
            wl[oi * 65 + ci] = W[(size_t)(o0 + oi) * Cn + c0 + ci];
        }
        for (int e = t; e < 4096; e += 256) {
            const int ki = e >> 6, ci = e & 63;
            cls[ki * 64 + ci] = g_cl[((size_t)b * Kn + ki) * Cn + c0 + ci];
        }
        __syncthreads();
        for (int ci = 0; ci < 64; ci++) {
            const float wv = wl[oL * 65 + ci];
#pragma unroll
            for (int kk = 0; kk < 8; kk++)
                acc[kk] = fmaf(wv, cls[(kset + kk) * 64 + ci], acc[kk]);
        }
        __syncthreads();
    }
#pragma unroll
    for (int kk = 0; kk < 8; kk++)
        g_wcl[((size_t)b * Cn + o0 + oL) * Kn + kset + kk] = acc[kk];
}

// ---------------- K5a: split W into bf16 hi/lo --------------------------------
__global__ void k_splitW(const float* __restrict__ W) {
    const int i = (blockIdx.x * 256 + threadIdx.x) * 2;
    const float2 v = *(const float2*)(W + i);
    __nv_bfloat16 h0 = __float2bfloat16(v.x), h1 = __float2bfloat16(v.y);
    __nv_bfloat162 hh; hh.x = h0; hh.y = h1;
    __nv_bfloat162 ll;
    ll.x = __float2bfloat16(v.x - __bfloat162float(h0));
    ll.y = __float2bfloat16(v.y - __bfloat162float(h1));
    *(__nv_bfloat162*)(g_wh + i) = hh;
    *(__nv_bfloat162*)(g_wl + i) = ll;
}

// ---------------- K5b: transpose + split x into bf16 hi/lo [b][p][c] ----------
__global__ void k_splitX(const float* __restrict__ x) {
    __shared__ float tile[32][65];   // [pj][ci]
    const int b = blockIdx.z, p0 = blockIdx.x * 32, c0 = blockIdx.y * 64;
    const int t = threadIdx.x;
    for (int e = t; e < 2048; e += 256) {
        const int ci = e >> 5, pj = e & 31;
        tile[pj][ci] = x[((size_t)b * Cn + c0 + ci) * HWn + p0 + pj];
    }
    __syncthreads();
    for (int e = t; e < 1024; e += 256) {
        const int pj = e >> 5, c2 = (e & 31) * 2;
        const float v0 = tile[pj][c2], v1 = tile[pj][c2 + 1];
        __nv_bfloat16 h0 = __float2bfloat16(v0), h1 = __float2bfloat16(v1);
        __nv_bfloat162 hh; hh.x = h0; hh.y = h1;
        __nv_bfloat162 ll;
        ll.x = __float2bfloat16(v0 - __bfloat162float(h0));
        ll.y = __float2bfloat16(v1 - __bfloat162float(h1));
        const size_t dst = ((size_t)b * HWn + p0 + pj) * Cn + c0 + c2;
        *(__nv_bfloat162*)(g_xth + dst) = hh;
        *(__nv_bfloat162*)(g_xtl + dst) = ll;
    }
}

// ---------------- K5c: per-pixel ||x||^2 --------------------------------------
__global__ void k_xsq(const float* __restrict__ x) {
    const int b = blockIdx.y;
    const int p = blockIdx.x * 256 + threadIdx.x;
    const float* xb = x + (size_t)b * Cn * HWn + p;
    float acc = 0.f;
#pragma unroll 8
    for (int c = 0; c < Cn; c++) {
        const float v = xb[(size_t)c * HWn];
        acc = fmaf(v, v, acc);
    }
    g_xsq[b * HWn + p] = acc;
}

// ---------------- K6: HMMA (mma.sync bf16 split) GEMM + fused epilogue --------
#define TILE_B  (128 * PT * 2)       // 10240 B per operand tile
#define STAGE_B (4 * TILE_B)         // Ah, Al, Bh, Bl
#define NCH     (Cn / 32)            // 32 k-chunks of 32
#define GEMM_SMEM (2 * STAGE_B)      // 81920 B

__device__ __forceinline__ void load_chunk(uint32_t base, int b, int o0, int p0,
                                           int k0, int t) {
#pragma unroll
    for (int e = t; e < 512; e += 256) {
        const int row = e >> 2, g = e & 3;
        const uint32_t d = base + row * (PT * 2) + g * 16;
        const size_t sA = (size_t)(o0 + row) * Cn + k0 + g * 8;
        cpa16(d,              g_wh + sA);
        cpa16(d + TILE_B,     g_wl + sA);
        const size_t sB = ((size_t)b * HWn + p0 + row) * Cn + k0 + g * 8;
        cpa16(d + 2 * TILE_B, g_xth + sB);
        cpa16(d + 3 * TILE_B, g_xtl + sB);
    }
}

__global__ __launch_bounds__(256, 1) void k_gemm_mma(const float* __restrict__ bias,
                                                     float* __restrict__ out) {
    extern __shared__ __align__(128) char smem[];
    const uint32_t sbase = smem_u32(smem);
    const int t = threadIdx.x;
    const int wid = t >> 5, lane = t & 31;
    const int wm = wid >> 2, wn = wid & 3;      // warp tile: 64(o) x 32(p)
    const int b  = blockIdx.z;
    const int o0 = blockIdx.y * 128;
    const int p0 = blockIdx.x * 128;

    const int alr = lane & 15, alc = (lane >> 4) << 3;
    const uint32_t a_lane = (uint32_t)(((wm * 64 + alr) * PT + alc) * 2);
    const int brow = ((lane >> 4) << 3) + (lane & 7);
    const int bkc  = ((lane >> 3) & 1) << 3;
    const uint32_t b_lane = (uint32_t)(((wn * 32 + brow) * PT + bkc) * 2);

    float acc[4][4][4];
#pragma unroll
    for (int i = 0; i < 4; i++)
#pragma unroll
        for (int j = 0; j < 4; j++)
#pragma unroll
            for (int q = 0; q < 4; q++) acc[i][j][q] = 0.f;

    load_chunk(sbase, b, o0, p0, 0, t);  CP_COMMIT();
    load_chunk(sbase + STAGE_B, b, o0, p0, 32, t);  CP_COMMIT();

    for (int c = 0; c < NCH; c++) {
        CP_WAIT1();
        __syncthreads();
        const uint32_t st = sbase + (c & 1) * STAGE_B;
#pragma unroll
        for (int ks = 0; ks < 2; ks++) {
            uint32_t bh[8], bl[8];
            ldsm_x4(bh + 0, st + 2 * TILE_B + b_lane + ks * 32);
            ldsm_x4(bh + 4, st + 2 * TILE_B + b_lane + 16 * PT * 2 + ks * 32);
            ldsm_x4(bl + 0, st + 3 * TILE_B + b_lane + ks * 32);
            ldsm_x4(bl + 4, st + 3 * TILE_B + b_lane + 16 * PT * 2 + ks * 32);
#pragma unroll
            for (int mf = 0; mf < 4; mf++) {
                uint32_t ah[4], al[4];
                ldsm_x4(ah, st + a_lane + mf * 16 * PT * 2 + ks * 32);
                ldsm_x4(al, st + TILE_B + a_lane + mf * 16 * PT * 2 + ks * 32);
#pragma unroll
                for (int nf = 0; nf < 4; nf++) {
                    mma16816(acc[mf][nf], ah, &bh[nf * 2]);
                    mma16816(acc[mf][nf], ah, &bl[nf * 2]);
                    mma16816(acc[mf][nf], al, &bh[nf * 2]);
                }
            }
        }
        __syncthreads();
        if (c + 2 < NCH)
            load_chunk(sbase + (c & 1) * STAGE_B, b, o0, p0, (c + 2) * 32, t);
        CP_COMMIT();
    }
    CP_WAIT0();
    __syncthreads();

    float* wcl_s  = (float*)smem;            // [128][65]
    float* bias_s = wcl_s + 128 * 65;
    float* wp_s   = bias_s + 128;
    int*   kid_s  = (int*)(wp_s + 128);
    for (int e = t; e < 128 * Kn; e += 256) {
        const int oi = e >> 6, k = e & 63;
        wcl_s[oi * 65 + k] = g_wcl[(size_t)b * Cn * Kn + (size_t)(o0 + oi) * Kn + k];
    }
    if (t < 128) {
        bias_s[t] = bias[o0 + t];
        wp_s[t]   = g_wmap[b * HWn + p0 + t];
        kid_s[t]  = g_idx[b * HWn + p0 + t];
    }
    __syncthreads();

    const int ql = lane >> 2, rl = (lane & 3) * 2;
#pragma unroll
    for (int mf = 0; mf < 4; mf++) {
        const int r0 = wm * 64 + mf * 16 + ql;
        const float bi0 = bias_s[r0], bi1 = bias_s[r0 + 8];
        const float* w0 = &wcl_s[r0 * 65];
        const float* w1 = w0 + 8 * 65;
        float* op0 = out + ((size_t)b * Cn + o0 + r0) * HWn + p0;
        float* op1 = op0 + (size_t)8 * HWn;
#pragma unroll
        for (int nf = 0; nf < 4; nf++) {
            const int cc = wn * 32 + nf * 8 + rl;
            const float wpa = wp_s[cc], wpb = wp_s[cc + 1];
            const int   ka  = kid_s[cc], kb = kid_s[cc + 1];
            const float* d = acc[mf][nf];
            float2 v0, v1;
            v0.x = fmaxf(d[0] + wpa * (w0[ka] - d[0]) + bi0, 0.f);
            v0.y = fmaxf(d[1] + wpb * (w0[kb] - d[1]) + bi0, 0.f);
            v1.x = fmaxf(d[2] + wpa * (w1[ka] - d[2]) + bi1, 0.f);
            v1.y = fmaxf(d[3] + wpb * (w1[kb] - d[3]) + bi1, 0.f);
            *(float2*)(op0 + cc) = v0;
            *(float2*)(op1 + cc) = v1;
        }
    }
}

// ---------------- launch -----------------------------------------------------
extern "C" void kernel_launch(void* const* d_in, const int* in_sizes, int n_in,
                              void* d_out, int out_size) {
    const float* x    = (const float*)d_in[0];
    const float* cent = (const float*)d_in[1];
    const float* W    = (const float*)d_in[2];
    const float* bias = (const float*)d_in[3];
    float* out = (float*)d_out;

    cudaFuncSetAttribute(k_gemm_mma, cudaFuncAttributeMaxDynamicSharedMemorySize, GEMM_SMEM);
    cudaFuncSetAttribute(k_score_argmax, cudaFuncAttributeMaxDynamicSharedMemorySize, SC_SMEM);
    cudaFuncSetAttribute(k_score_wmap, cudaFuncAttributeMaxDynamicSharedMemorySize, SC_SMEM);

    k_splitW <<<Cn * Cn / 512, 256>>>(W);
    k_splitX <<<dim3(HWn / 32, Cn / 64, Bn), 256>>>(x);
    k_xsq    <<<dim3(HWn / 256, Bn), 256>>>(x);
    k_prep   <<<Kn, 256>>>(cent);
    k_score_argmax<<<dim3(HWn / 128, Bn), 256, SC_SMEM>>>();
    k_prefix <<<Bn, 32>>>();
    k_scatter<<<dim3(HWn / 256, Bn), 256>>>();
    k_cl     <<<dim3(Cn / 2, Bn), 256>>>(x);
    k_clsplit<<<Bn * Kn, 256>>>();
    k_wcl    <<<dim3(Cn / 32, Bn), 256>>>(W);
    k_score_wmap<<<dim3(HWn / 128, Bn), 256, SC_SMEM>>>();
    k_gemm_mma<<<dim3(HWn / 128, Cn / 128, Bn), 256, GEMM_SMEM>>>(bias, out);
}

// round 10
// speedup vs baseline: 2.6832x; 1.4857x over previous
#include <cuda_runtime.h>
#include <cuda_fp16.h>
#include <cstdint>

#define Bn  8
#define Cn  1024
#define HWn 4096
#define Kn  64

// ---------------- device scratch (no allocations allowed) ----------------
__device__ int   g_idx[Bn * HWn];      // argmax cluster per pixel
__device__ int   g_counts[Bn * Kn];
__device__ int   g_base[Bn * Kn];
__device__ int   g_cursor[Bn * Kn];
__device__ int   g_order[Bn * HWn];    // pixel ids grouped by cluster (per batch)
__device__ float g_cl[Bn * Kn * Cn];   // local centroids [b][k][c]
__device__ float g_wcl[Bn * Cn * Kn];  // W @ cl^T  [b][o][k]
__device__ float g_wmap[Bn * HWn];     // calibration weight per pixel
__device__ float g_xsq[Bn * HWn];      // ||x_p||^2
__device__ float g_clsq[Bn * Kn];      // ||cl_k||^2

// fp16 hi/lo split operands
__device__ __half g_wh[Cn * Cn];                       // W hi, [o][c]
__device__ __half g_xh[(size_t)Bn * HWn * Cn];         // x^T hi, [b][p][c]
__device__ __half g_xl[(size_t)Bn * HWn * Cn];         // x^T lo
__device__ __half g_cnh[Kn * Cn];                      // normalized centroids hi [k][c]
__device__ __half g_cnl[Kn * Cn];                      // normalized centroids lo
__device__ __half g_clh[Bn * Kn * Cn];                 // local centroids hi [b][k][c]

// ---------------- baseline-PTX helpers (compute_103-safe) ----------------
__device__ __forceinline__ uint32_t smem_u32(const void* p) {
    uint32_t a;
    asm("{ .reg .u64 t; cvta.to.shared.u64 t, %1; cvt.u32.u64 %0, t; }" : "=r"(a) : "l"(p));
    return a;
}
__device__ __forceinline__ void cpa16(uint32_t dst, const void* src) {
    asm volatile("cp.async.cg.shared.global [%0], [%1], 16;"
                 :: "r"(dst), "l"(__cvta_generic_to_global(src)) : "memory");
}
#define CP_COMMIT() asm volatile("cp.async.commit_group;" ::: "memory")
#define CP_WAIT1()  asm volatile("cp.async.wait_group 1;" ::: "memory")
#define CP_WAIT0()  asm volatile("cp.async.wait_group 0;" ::: "memory")

__device__ __forceinline__ void ldsm_x4(uint32_t* r, uint32_t addr) {
    asm volatile("ldmatrix.sync.aligned.m8n8.x4.shared.b16 {%0,%1,%2,%3}, [%4];"
                 : "=r"(r[0]), "=r"(r[1]), "=r"(r[2]), "=r"(r[3]) : "r"(addr));
}
__device__ __forceinline__ void mma16816(float* d, const uint32_t* a, const uint32_t* b) {
    asm volatile("mma.sync.aligned.m16n8k16.row.col.f32.f16.f16.f32 "
                 "{%0,%1,%2,%3}, {%4,%5,%6,%7}, {%8,%9}, {%0,%1,%2,%3};"
                 : "+f"(d[0]), "+f"(d[1]), "+f"(d[2]), "+f"(d[3])
                 : "r"(a[0]), "r"(a[1]), "r"(a[2]), "r"(a[3]), "r"(b[0]), "r"(b[1]));
}

// ---------------- K0: normalize centroids -> fp16 hi/lo [k][c]; zero counts ---
__global__ void k_prep(const float* __restrict__ cent) {
    const int kk = blockIdx.x;
    const int t  = threadIdx.x;
    __shared__ float red[256];
    float s = 0.f;
    for (int c = t; c < Cn; c += 256) { float v = cent[kk * Cn + c]; s = fmaf(v, v, s); }
    red[t] = s; __syncthreads();
    for (int o = 128; o; o >>= 1) { if (t < o) red[t] += red[t + o]; __syncthreads(); }
    const float scale = 1.f / fmaxf(sqrtf(red[0]), 1e-12f);
    for (int c = t; c < Cn; c += 256) {
        const float v = cent[kk * Cn + c] * scale;
        const __half h = __float2half_rn(v);
        g_cnh[kk * Cn + c] = h;
        g_cnl[kk * Cn + c] = __float2half_rn(v - __half2float(h));
    }
    if (blockIdx.x == 0 && t < 256) { g_counts[t] = 0; g_counts[256 + t] = 0; }
}

// ---------------- score kernels: S[128p x 64k] = A . B^T via fp16 MMA --------
#define PT      40                   // SMEM pitch in fp16 elems (80 B)
#define SC_AT   (128 * PT * 2)       // 10240 B per A tile
#define SC_BT   (64 * PT * 2)        // 5120 B per B tile
#define SC_STAGE (2 * SC_AT + 2 * SC_BT)   // 30720
#define SC_SMEM  (2 * SC_STAGE)            // 61440
#define SC_NCH   (Cn / 32)

template <bool THREE>
__device__ __forceinline__ void sc_load(uint32_t base,
                                        const __half* Ah, const __half* Al,
                                        const __half* Bh, const __half* Bl,
                                        int k0, int t) {
#pragma unroll
    for (int e = t; e < 512; e += 256) {
        const int row = e >> 2, g = e & 3;
        const uint32_t d = base + row * (PT * 2) + g * 16;
        const size_t s = (size_t)row * Cn + k0 + g * 8;
        cpa16(d,         Ah + s);
        cpa16(d + SC_AT, Al + s);
    }
    {
        const int row = t >> 2, g = t & 3;
        const uint32_t d = base + 2 * SC_AT + row * (PT * 2) + g * 16;
        const size_t s = (size_t)row * Cn + k0 + g * 8;
        cpa16(d, Bh + s);
        if (THREE) cpa16(d + SC_BT, Bl + s);
    }
}

// computes S into sS[128][66] (fp32)
// THREE: Ah.Bh + Ah.Bl + Al.Bh   TWO: Ah.Bh + Al.Bh
template <bool THREE>
__device__ __forceinline__ void sc_compute(char* smem, float* sS,
                                           const __half* Ah, const __half* Al,
                                           const __half* Bh, const __half* Bl,
                                           int t) {
    const uint32_t sbase = smem_u32(smem);
    const int wid = t >> 5, lane = t & 31;
    const int wm = wid >> 1, wn = wid & 1;       // warp tile 32p x 32k
    const int alr = lane & 15, alc = (lane >> 4) << 3;
    const uint32_t a_lane = (uint32_t)(((wm * 32 + alr) * PT + alc) * 2);
    const int brow = ((lane >> 4) << 3) + (lane & 7);
    const int bkc  = ((lane >> 3) & 1) << 3;
    const uint32_t b_lane = (uint32_t)(((wn * 32 + brow) * PT + bkc) * 2);

    float acc[2][4][4];
#pragma unroll
    for (int i = 0; i < 2; i++)
#pragma unroll
        for (int j = 0; j < 4; j++)
#pragma unroll
            for (int q = 0; q < 4; q++) acc[i][j][q] = 0.f;

    sc_load<THREE>(sbase, Ah, Al, Bh, Bl, 0, t);  CP_COMMIT();
    sc_load<THREE>(sbase + SC_STAGE, Ah, Al, Bh, Bl, 32, t);  CP_COMMIT();

    for (int c = 0; c < SC_NCH; c++) {
        CP_WAIT1();
        __syncthreads();
        const uint32_t st = sbase + (c & 1) * SC_STAGE;
#pragma unroll
        for (int ks = 0; ks < 2; ks++) {
            uint32_t bh[8], bl[8];
            ldsm_x4(bh + 0, st + 2 * SC_AT + b_lane + ks * 32);
            ldsm_x4(bh + 4, st + 2 * SC_AT + b_lane + 16 * PT * 2 + ks * 32);
            if (THREE) {
                ldsm_x4(bl + 0, st + 2 * SC_AT + SC_BT + b_lane + ks * 32);
                ldsm_x4(bl + 4, st + 2 * SC_AT + SC_BT + b_lane + 16 * PT * 2 + ks * 32);
            }
#pragma unroll
            for (int mf = 0; mf < 2; mf++) {
                uint32_t ah[4], al[4];
                ldsm_x4(ah, st + a_lane + mf * 16 * PT * 2 + ks * 32);
                ldsm_x4(al, st + SC_AT + a_lane + mf * 16 * PT * 2 + ks * 32);
#pragma unroll
                for (int nf = 0; nf < 4; nf++) {
                    mma16816(acc[mf][nf], ah, &bh[nf * 2]);
                    if (THREE) mma16816(acc[mf][nf], ah, &bl[nf * 2]);
                    mma16816(acc[mf][nf], al, &bh[nf * 2]);
                }
            }
        }
        __syncthreads();
        if (c + 2 < SC_NCH)
            sc_load<THREE>(sbase + (c & 1) * SC_STAGE, Ah, Al, Bh, Bl, (c + 2) * 32, t);
        CP_COMMIT();
    }
    CP_WAIT0();
    __syncthreads();

    const int ql = lane >> 2, rl = (lane & 3) * 2;
#pragma unroll
    for (int mf = 0; mf < 2; mf++) {
        const int row = wm * 32 + mf * 16 + ql;
#pragma unroll
        for (int nf = 0; nf < 4; nf++) {
            const int col = wn * 32 + nf * 8 + rl;
            const float* d = acc[mf][nf];
            sS[row * 66 + col]           = d[0];
            sS[row * 66 + col + 1]       = d[1];
            sS[(row + 8) * 66 + col]     = d[2];
            sS[(row + 8) * 66 + col + 1] = d[3];
        }
    }
    __syncthreads();
}

// K1: nearest-centroid assignment (3-term: flip-sensitive, keep high precision)
__global__ __launch_bounds__(256, 2) void k_score_argmax() {
    extern __shared__ __align__(128) char smem[];
    float* sS = (float*)smem;
    int* hist = (int*)(smem + 128 * 66 * 4);
    const int t = threadIdx.x;
    const int b = blockIdx.y;
    const int p0 = blockIdx.x * 128;
    const __half* Ah = g_xh + ((size_t)b * HWn + p0) * Cn;
    const __half* Al = g_xl + ((size_t)b * HWn + p0) * Cn;

    sc_compute<true>(smem, sS, Ah, Al, g_cnh, g_cnl, t);

    if (t < Kn) hist[t] = 0;
    __syncthreads();
    if (t < 128) {
        const float* row = sS + t * 66;
        float best = row[0]; int bi = 0;
#pragma unroll
        for (int k = 1; k < Kn; k++) { const float v = row[k]; if (v > best) { best = v; bi = k; } }
        g_idx[b * HWn + p0 + t] = bi;
        atomicAdd(&hist[bi], 1);
    }
    __syncthreads();
    if (t < Kn && hist[t]) atomicAdd(&g_counts[b * Kn + t], hist[t]);
}

// K4: calibration weight map (2-term: smooth path, fp16 hi suffices)
__global__ __launch_bounds__(256, 2) void k_score_wmap() {
    extern __shared__ __align__(128) char smem[];
    float* sS = (float*)smem;
    float* clsq_s = (float*)(smem + 128 * 66 * 4);
    const int t = threadIdx.x;
    const int b = blockIdx.y;
    const int p0 = blockIdx.x * 128;
    const __half* Ah = g_xh + ((size_t)b * HWn + p0) * Cn;
    const __half* Al = g_xl + ((size_t)b * HWn + p0) * Cn;
    const __half* Bh = g_clh + (size_t)b * Kn * Cn;

    sc_compute<false>(smem, sS, Ah, Al, Bh, Bh, t);

    if (t < Kn) clsq_s[t] = g_clsq[b * Kn + t];
    __syncthreads();
    if (t < 128) {
        const int p = p0 + t;
        const int k = g_idx[b * HWn + p];
        const float D = sS[t * 66 + k];
        const float q = g_xsq[b * HWn + p] - 2.f * D + clsq_s[k];
        g_wmap[b * HWn + p] = expf(-q * (1.f / 1024.f));
    }
}

// ---------------- K1b: per-batch exclusive prefix -----------------------------
__global__ void k_prefix() {
    const int b = blockIdx.x;
    if (threadIdx.x == 0) {
        int acc = 0;
        for (int k = 0; k < Kn; k++) {
            g_base[b * Kn + k]   = acc;
            g_cursor[b * Kn + k] = acc;
            acc += g_counts[b * Kn + k];
        }
    }
}

// ---------------- K1c: scatter pixel ids grouped by cluster ------------------
__global__ void k_scatter() {
    const int b = blockIdx.y;
    const int p = blockIdx.x * 256 + threadIdx.x;
    const int k = g_idx[b * HWn + p];
    const int pos = atomicAdd(&g_cursor[b * Kn + k], 1);
    g_order[b * HWn + pos] = p;
}

// ---------------- K2: local centroids via gather ------------------------------
__global__ void k_cl(const float* __restrict__ x) {
    __shared__ float xr[2 * HWn];
    const int b  = blockIdx.y;
    const int c0 = blockIdx.x * 2;
    const int t  = threadIdx.x;
    for (int e = t; e < 2 * HWn; e += 256)
        xr[e] = x[((size_t)b * Cn + c0 + (e >> 12)) * HWn + (e & (HWn - 1))];
    __syncthreads();
    const int warp = t >> 5, lane = t & 31;
    for (int k = warp; k < Kn; k += 8) {
        const int n   = g_counts[b * Kn + k];
        const int bas = g_base[b * Kn + k];
        float s0 = 0.f, s1 = 0.f;
        for (int i = lane; i < n; i += 32) {
            const int pix = g_order[b * HWn + bas + i];
            s0 += xr[pix];
            s1 += xr[HWn + pix];
        }
#pragma unroll
        for (int off = 16; off; off >>= 1) {
            s0 += __shfl_xor_sync(0xffffffffu, s0, off);
            s1 += __shfl_xor_sync(0xffffffffu, s1, off);
        }
        if (lane == 0) {
            const float inv = 1.f / (float)max(n, 1);
            g_cl[((size_t)b * Kn + k) * Cn + c0 + 0] = s0 * inv;
            g_cl[((size_t)b * Kn + k) * Cn + c0 + 1] = s1 * inv;
        }
    }
}

// ---------------- K2b: local centroids -> fp16 hi + ||cl||^2 ------------------
__global__ void k_clsplit() {
    const int bk = blockIdx.x;           // b*Kn + k
    const int t  = threadIdx.x;
    __shared__ float red[256];
    float s = 0.f;
    for (int c = t; c < Cn; c += 256) {
        const float v = g_cl[(size_t)bk * Cn + c];
        g_clh[(size_t)bk * Cn + c] = __float2half_rn(v);
        s = fmaf(v, v, s);
    }
    red[t] = s; __syncthreads();
    for (int o = 128; o; o >>= 1) { if (t < o) red[t] += red[t + o]; __syncthreads(); }
    if (t == 0) g_clsq[bk] = red[0];
}

// ---------------- K3: Wcl[b,o,k] = sum_c W[o,c] * cl[b,k,c] ------------------
__global__ void k_wcl(const float* __restrict__ W) {
    __shared__ float wl[32 * 65];
    __shared__ float cls[64 * 64];
    const int b = blockIdx.y, o0 = blockIdx.x * 32, t = threadIdx.x;
    const int oL = t & 31, kset = (t >> 5) * 8;
    float acc[8];
#pragma unroll
    for (int i = 0; i < 8; i++) acc[i] = 0.f;
    for (int c0 = 0; c0 < Cn; c0 += 64) {
        for (int e = t; e < 2048; e += 256) {
            const int oi = e >> 6, ci = e & 63;
            wl[oi * 65 + ci] = W[(size_t)(o0 + oi) * Cn + c0 + ci];
        }
        for (int e = t; e < 4096; e += 256) {
            const int ki = e >> 6, ci = e & 63;
            cls[ki * 64 + ci] = g_cl[((size_t)b * Kn + ki) * Cn + c0 + ci];
        }
        __syncthreads();
        for (int ci = 0; ci < 64; ci++) {
            const float wv = wl[oL * 65 + ci];
#pragma unroll
            for (int kk = 0; kk < 8; kk++)
                acc[kk] = fmaf(wv, cls[(kset + kk) * 64 + ci], acc[kk]);
        }
        __syncthreads();
    }
#pragma unroll
    for (int kk = 0; kk < 8; kk++)
        g_wcl[((size_t)b * Cn + o0 + oL) * Kn + kset + kk] = acc[kk];
}

// ---------------- K5a: W -> fp16 hi ------------------------------------------
__global__ void k_splitW(const float* __restrict__ W) {
    const int i = (blockIdx.x * 256 + threadIdx.x) * 2;
    const float2 v = *(const float2*)(W + i);
    __half2 hh; hh.x = __float2half_rn(v.x); hh.y = __float2half_rn(v.y);
    *(__half2*)(g_wh + i) = hh;
}

// ---------------- K5b: transpose + split x into fp16 hi/lo [b][p][c] ----------
__global__ void k_splitX(const float* __restrict__ x) {
    __shared__ float tile[32][65];   // [pj][ci]
    const int b = blockIdx.z, p0 = blockIdx.x * 32, c0 = blockIdx.y * 64;
    const int t = threadIdx.x;
    for (int e = t; e < 2048; e += 256) {
        const int ci = e >> 5, pj = e & 31;
        tile[pj][ci] = x[((size_t)b * Cn + c0 + ci) * HWn + p0 + pj];
    }
    __syncthreads();
    for (int e = t; e < 1024; e += 256) {
        const int pj = e >> 5, c2 = (e & 31) * 2;
        const float v0 = tile[pj][c2], v1 = tile[pj][c2 + 1];
        const __half h0 = __float2half_rn(v0), h1 = __float2half_rn(v1);
        __half2 hh; hh.x = h0; hh.y = h1;
        __half2 ll;
        ll.x = __float2half_rn(v0 - __half2float(h0));
        ll.y = __float2half_rn(v1 - __half2float(h1));
        const size_t dst = ((size_t)b * HWn + p0 + pj) * Cn + c0 + c2;
        *(__half2*)(g_xh + dst) = hh;
        *(__half2*)(g_xl + dst) = ll;
    }
}

// ---------------- K5c: ||x_p||^2 from coalesced split arrays ------------------
__global__ void k_xsq2() {
    const int wid = threadIdx.x >> 5, lane = threadIdx.x & 31;
    const int row = blockIdx.x * 8 + wid;         // over Bn*HWn
    const __half2* h2 = (const __half2*)(g_xh + (size_t)row * Cn);
    const __half2* l2 = (const __half2*)(g_xl + (size_t)row * Cn);
    float acc = 0.f;
#pragma unroll 4
    for (int i = lane; i < Cn / 2; i += 32) {
        const float2 h = __half22float2(h2[i]);
        const float2 l = __half22float2(l2[i]);
        const float v0 = h.x + l.x, v1 = h.y + l.y;
        acc = fmaf(v0, v0, acc);
        acc = fmaf(v1, v1, acc);
    }
#pragma unroll
    for (int off = 16; off; off >>= 1) acc += __shfl_xor_sync(0xffffffffu, acc, off);
    if (lane == 0) g_xsq[row] = acc;
}

// ---------------- K6: fp16 2-term HMMA GEMM + fused epilogue ------------------
// D[128 o, 128 p] = Wh[o,c] * (Xh + Xl)[p,c]  (drop Wl.X term, ~2.8e-4 rel)
#define A_T     10240                // Wh tile
#define B_T     10240                // each of Xh, Xl tiles
#define STAGE_B (A_T + 2 * B_T)      // 30720
#define NCH     (Cn / 32)
#define GEMM_SMEM (2 * STAGE_B)      // 61440

__device__ __forceinline__ void load_chunk(uint32_t base, int b, int o0, int p0,
                                           int k0, int t) {
#pragma unroll
    for (int e = t; e < 512; e += 256) {
        const int row = e >> 2, g = e & 3;
        const uint32_t d = base + row * (PT * 2) + g * 16;
        cpa16(d, g_wh + (size_t)(o0 + row) * Cn + k0 + g * 8);
    }
#pragma unroll
    for (int e = t; e < 512; e += 256) {
        const int row = e >> 2, g = e & 3;
        const uint32_t d = base + A_T + row * (PT * 2) + g * 16;
        const size_t s = ((size_t)b * HWn + p0 + row) * Cn + k0 + g * 8;
        cpa16(d,       g_xh + s);
        cpa16(d + B_T, g_xl + s);
    }
}

__global__ __launch_bounds__(256, 2) void k_gemm_mma(const float* __restrict__ bias,
                                                     float* __restrict__ out) {
    extern __shared__ __align__(128) char smem[];
    const uint32_t sbase = smem_u32(smem);
    const int t = threadIdx.x;
    const int wid = t >> 5, lane = t & 31;
    const int wm = wid >> 2, wn = wid & 3;      // warp tile: 64(o) x 32(p)
    const int b  = blockIdx.z;
    const int o0 = blockIdx.y * 128;
    const int p0 = blockIdx.x * 128;

    const int alr = lane & 15, alc = (lane >> 4) << 3;
    const uint32_t a_lane = (uint32_t)(((wm * 64 + alr) * PT + alc) * 2);
    const int brow = ((lane >> 4) << 3) + (lane & 7);
    const int bkc  = ((lane >> 3) & 1) << 3;
    const uint32_t b_lane = (uint32_t)(((wn * 32 + brow) * PT + bkc) * 2);

    float acc[4][4][4];
#pragma unroll
    for (int i = 0; i < 4; i++)
#pragma unroll
        for (int j = 0; j < 4; j++)
#pragma unroll
            for (int q = 0; q < 4; q++) acc[i][j][q] = 0.f;

    load_chunk(sbase, b, o0, p0, 0, t);  CP_COMMIT();
    load_chunk(sbase + STAGE_B, b, o0, p0, 32, t);  CP_COMMIT();

    for (int c = 0; c < NCH; c++) {
        CP_WAIT1();
        __syncthreads();
        const uint32_t st = sbase + (c & 1) * STAGE_B;
#pragma unroll
        for (int ks = 0; ks < 2; ks++) {
            uint32_t bh[8], bl[8];
            ldsm_x4(bh + 0, st + A_T + b_lane + ks * 32);
            ldsm_x4(bh + 4, st + A_T + b_lane + 16 * PT * 2 + ks * 32);
            ldsm_x4(bl + 0, st + A_T + B_T + b_lane + ks * 32);
            ldsm_x4(bl + 4, st + A_T + B_T + b_lane + 16 * PT * 2 + ks * 32);
#pragma unroll
            for (int mf = 0; mf < 4; mf++) {
                uint32_t ah[4];
                ldsm_x4(ah, st + a_lane + mf * 16 * PT * 2 + ks * 32);
#pragma unroll
                for (int nf = 0; nf < 4; nf++) {
                    mma16816(acc[mf][nf], ah, &bh[nf * 2]);
                    mma16816(acc[mf][nf], ah, &bl[nf * 2]);
                }
            }
        }
        __syncthreads();
        if (c + 2 < NCH)
            load_chunk(sbase + (c & 1) * STAGE_B, b, o0, p0, (c + 2) * 32, t);
        CP_COMMIT();
    }
    CP_WAIT0();
    __syncthreads();

    float* wcl_s  = (float*)smem;            // [128][65]
    float* bias_s = wcl_s + 128 * 65;
    float* wp_s   = bias_s + 128;
    int*   kid_s  = (int*)(wp_s + 128);
    for (int e = t; e < 128 * Kn; e += 256) {
        const int oi = e >> 6, k = e & 63;
        wcl_s[oi * 65 + k] = g_wcl[(size_t)b * Cn * Kn + (size_t)(o0 + oi) * Kn + k];
    }
    if (t < 128) {
        bias_s[t] = bias[o0 + t];
        wp_s[t]   = g_wmap[b * HWn + p0 + t];
        kid_s[t]  = g_idx[b * HWn + p0 + t];
    }
    __syncthreads();

    const int ql = lane >> 2, rl = (lane & 3) * 2;
#pragma unroll
    for (int mf = 0; mf < 4; mf++) {
        const int r0 = wm * 64 + mf * 16 + ql;
        const float bi0 = bias_s[r0], bi1 = bias_s[r0 + 8];
        const float* w0 = &wcl_s[r0 * 65];
        const float* w1 = w0 + 8 * 65;
        float* op0 = out + ((size_t)b * Cn + o0 + r0) * HWn + p0;
        float* op1 = op0 + (size_t)8 * HWn;
#pragma unroll
        for (int nf = 0; nf < 4; nf++) {
            const int cc = wn * 32 + nf * 8 + rl;
            const float wpa = wp_s[cc], wpb = wp_s[cc + 1];
            const int   ka  = kid_s[cc], kb = kid_s[cc + 1];
            const float* d = acc[mf][nf];
            float2 v0, v1;
            v0.x = fmaxf(d[0] + wpa * (w0[ka] - d[0]) + bi0, 0.f);
            v0.y = fmaxf(d[1] + wpb * (w0[kb] - d[1]) + bi0, 0.f);
            v1.x = fmaxf(d[2] + wpa * (w1[ka] - d[2]) + bi1, 0.f);
            v1.y = fmaxf(d[3] + wpb * (w1[kb] - d[3]) + bi1, 0.f);
            *(float2*)(op0 + cc) = v0;
            *(float2*)(op1 + cc) = v1;
        }
    }
}

// ---------------- launch -----------------------------------------------------
extern "C" void kernel_launch(void* const* d_in, const int* in_sizes, int n_in,
                              void* d_out, int out_size) {
    const float* x    = (const float*)d_in[0];
    const float* cent = (const float*)d_in[1];
    const float* W    = (const float*)d_in[2];
    const float* bias = (const float*)d_in[3];
    float* out = (float*)d_out;

    cudaFuncSetAttribute(k_gemm_mma, cudaFuncAttributeMaxDynamicSharedMemorySize, GEMM_SMEM);
    cudaFuncSetAttribute(k_score_argmax, cudaFuncAttributeMaxDynamicSharedMemorySize, SC_SMEM);
    cudaFuncSetAttribute(k_score_wmap, cudaFuncAttributeMaxDynamicSharedMemorySize, SC_SMEM);

    k_splitW <<<Cn * Cn / 512, 256>>>(W);
    k_splitX <<<dim3(HWn / 32, Cn / 64, Bn), 256>>>(x);
    k_xsq2   <<<Bn * HWn / 8, 256>>>();
    k_prep   <<<Kn, 256>>>(cent);
    k_score_argmax<<<dim3(HWn / 128, Bn), 256, SC_SMEM>>>();
    k_prefix <<<Bn, 32>>>();
    k_scatter<<<dim3(HWn / 256, Bn), 256>>>();
    k_cl     <<<dim3(Cn / 2, Bn), 256>>>(x);
    k_clsplit<<<Bn * Kn, 256>>>();
    k_wcl    <<<dim3(Cn / 32, Bn), 256>>>(W);
    k_score_wmap<<<dim3(HWn / 128, Bn), 256, SC_SMEM>>>();
    k_gemm_mma<<<dim3(HWn / 128, Cn / 128, Bn), 256, GEMM_SMEM>>>(bias, out);
}

// round 12
// speedup vs baseline: 3.6183x; 1.3485x over previous
#include <cuda_runtime.h>
#include <cuda_fp16.h>
#include <cstdint>

#define Bn  8
#define Cn  1024
#define HWn 4096
#define Kn  64

// ---------------- device scratch (no allocations allowed) ----------------
__device__ int   g_idx[Bn * HWn];      // argmax cluster per pixel
__device__ int   g_counts[Bn * Kn];
__device__ int   g_base[Bn * Kn];
__device__ int   g_cursor[Bn * Kn];
__device__ int   g_order[Bn * HWn];    // pixel ids grouped by cluster (per batch)
__device__ float g_cl[Bn * Kn * Cn];   // local centroids [b][k][c]
__device__ float g_wcl[Bn * Cn * Kn];  // W @ cl^T  [b][o][k]
__device__ float g_wmap[Bn * HWn];     // calibration weight per pixel

// fp16 hi/lo split operands
__device__ __half g_wh[Cn * Cn];                       // W hi, [o][c]
__device__ __half g_xh[(size_t)Bn * HWn * Cn];         // x^T hi, [b][p][c]
__device__ __half g_xl[(size_t)Bn * HWn * Cn];         // x^T lo
__device__ __half g_cnh[Kn * Cn];                      // normalized centroids hi [k][c]
__device__ __half g_cnl[Kn * Cn];                      // normalized centroids lo

// ---------------- baseline-PTX helpers (compute_103-safe) ----------------
__device__ __forceinline__ uint32_t smem_u32(const void* p) {
    uint32_t a;
    asm("{ .reg .u64 t; cvta.to.shared.u64 t, %1; cvt.u32.u64 %0, t; }" : "=r"(a) : "l"(p));
    return a;
}
__device__ __forceinline__ void cpa16(uint32_t dst, const void* src) {
    asm volatile("cp.async.cg.shared.global [%0], [%1], 16;"
                 :: "r"(dst), "l"(__cvta_generic_to_global(src)) : "memory");
}
#define CP_COMMIT() asm volatile("cp.async.commit_group;" ::: "memory")
#define CP_WAIT1()  asm volatile("cp.async.wait_group 1;" ::: "memory")
#define CP_WAIT2()  asm volatile("cp.async.wait_group 2;" ::: "memory")
#define CP_WAIT0()  asm volatile("cp.async.wait_group 0;" ::: "memory")

__device__ __forceinline__ void ldsm_x4(uint32_t* r, uint32_t addr) {
    asm volatile("ldmatrix.sync.aligned.m8n8.x4.shared.b16 {%0,%1,%2,%3}, [%4];"
                 : "=r"(r[0]), "=r"(r[1]), "=r"(r[2]), "=r"(r[3]) : "r"(addr));
}
__device__ __forceinline__ void mma16816(float* d, const uint32_t* a, const uint32_t* b) {
    asm volatile("mma.sync.aligned.m16n8k16.row.col.f32.f16.f16.f32 "
                 "{%0,%1,%2,%3}, {%4,%5,%6,%7}, {%8,%9}, {%0,%1,%2,%3};"
                 : "+f"(d[0]), "+f"(d[1]), "+f"(d[2]), "+f"(d[3])
                 : "r"(a[0]), "r"(a[1]), "r"(a[2]), "r"(a[3]), "r"(b[0]), "r"(b[1]));
}

// ---------------- K0: normalize centroids -> fp16 hi/lo [k][c]; zero counts ---
__global__ void k_prep(const float* __restrict__ cent) {
    const int kk = blockIdx.x;
    const int t  = threadIdx.x;
    __shared__ float red[256];
    float s = 0.f;
    for (int c = t; c < Cn; c += 256) { float v = cent[kk * Cn + c]; s = fmaf(v, v, s); }
    red[t] = s; __syncthreads();
    for (int o = 128; o; o >>= 1) { if (t < o) red[t] += red[t + o]; __syncthreads(); }
    const float scale = 1.f / fmaxf(sqrtf(red[0]), 1e-12f);
    for (int c = t; c < Cn; c += 256) {
        const float v = cent[kk * Cn + c] * scale;
        const __half h = __float2half_rn(v);
        g_cnh[kk * Cn + c] = h;
        g_cnl[kk * Cn + c] = __float2half_rn(v - __half2float(h));
    }
    if (blockIdx.x == 0 && t < 256) { g_counts[t] = 0; g_counts[256 + t] = 0; }
}

// ---------------- argmax score kernel: S[128p x 64k] via 3-term fp16 MMA ------
#define PT      40                   // SMEM pitch in fp16 elems (80 B)
#define SC_AT   (128 * PT * 2)       // 10240 B per A tile
#define SC_BT   (64 * PT * 2)        // 5120 B per B tile
#define SC_STAGE (2 * SC_AT + 2 * SC_BT)   // 30720
#define SC_SMEM  (2 * SC_STAGE)            // 61440
#define SC_NCH   (Cn / 32)

__device__ __forceinline__ void sc_load(uint32_t base,
                                        const __half* Ah, const __half* Al,
                                        const __half* Bh, const __half* Bl,
                                        int k0, int t) {
#pragma unroll
    for (int e = t; e < 512; e += 256) {
        const int row = e >> 2, g = e & 3;
        const uint32_t d = base + row * (PT * 2) + g * 16;
        const size_t s = (size_t)row * Cn + k0 + g * 8;
        cpa16(d,         Ah + s);
        cpa16(d + SC_AT, Al + s);
    }
    {
        const int row = t >> 2, g = t & 3;
        const uint32_t d = base + 2 * SC_AT + row * (PT * 2) + g * 16;
        const size_t s = (size_t)row * Cn + k0 + g * 8;
        cpa16(d,         Bh + s);
        cpa16(d + SC_BT, Bl + s);
    }
}

// S = Ah.Bh + Ah.Bl + Al.Bh  into sS[128][66]
__device__ __forceinline__ void sc_compute(char* smem, float* sS,
                                           const __half* Ah, const __half* Al,
                                           const __half* Bh, const __half* Bl,
                                           int t) {
    const uint32_t sbase = smem_u32(smem);
    const int wid = t >> 5, lane = t & 31;
    const int wm = wid >> 1, wn = wid & 1;       // warp tile 32p x 32k
    const int alr = lane & 15, alc = (lane >> 4) << 3;
    const uint32_t a_lane = (uint32_t)(((wm * 32 + alr) * PT + alc) * 2);
    const int brow = ((lane >> 4) << 3) + (lane & 7);
    const int bkc  = ((lane >> 3) & 1) << 3;
    const uint32_t b_lane = (uint32_t)(((wn * 32 + brow) * PT + bkc) * 2);

    float acc[2][4][4];
#pragma unroll
    for (int i = 0; i < 2; i++)
#pragma unroll
        for (int j = 0; j < 4; j++)
#pragma unroll
            for (int q = 0; q < 4; q++) acc[i][j][q] = 0.f;

    sc_load(sbase, Ah, Al, Bh, Bl, 0, t);  CP_COMMIT();
    sc_load(sbase + SC_STAGE, Ah, Al, Bh, Bl, 32, t);  CP_COMMIT();

    for (int c = 0; c < SC_NCH; c++) {
        CP_WAIT1();
        __syncthreads();
        const uint32_t st = sbase + (c & 1) * SC_STAGE;
#pragma unroll
        for (int ks = 0; ks < 2; ks++) {
            uint32_t bh[8], bl[8];
            ldsm_x4(bh + 0, st + 2 * SC_AT + b_lane + ks * 32);
            ldsm_x4(bh + 4, st + 2 * SC_AT + b_lane + 16 * PT * 2 + ks * 32);
            ldsm_x4(bl + 0, st + 2 * SC_AT + SC_BT + b_lane + ks * 32);
            ldsm_x4(bl + 4, st + 2 * SC_AT + SC_BT + b_lane + 16 * PT * 2 + ks * 32);
#pragma unroll
            for (int mf = 0; mf < 2; mf++) {
                uint32_t ah[4], al[4];
                ldsm_x4(ah, st + a_lane + mf * 16 * PT * 2 + ks * 32);
                ldsm_x4(al, st + SC_AT + a_lane + mf * 16 * PT * 2 + ks * 32);
#pragma unroll
                for (int nf = 0; nf < 4; nf++) {
                    mma16816(acc[mf][nf], ah, &bh[nf * 2]);
                    mma16816(acc[mf][nf], ah, &bl[nf * 2]);
                    mma16816(acc[mf][nf], al, &bh[nf * 2]);
                }
            }
        }
        __syncthreads();
        if (c + 2 < SC_NCH)
            sc_load(sbase + (c & 1) * SC_STAGE, Ah, Al, Bh, Bl, (c + 2) * 32, t);
        CP_COMMIT();
    }
    CP_WAIT0();
    __syncthreads();

    const int ql = lane >> 2, rl = (lane & 3) * 2;
#pragma unroll
    for (int mf = 0; mf < 2; mf++) {
        const int row = wm * 32 + mf * 16 + ql;
#pragma unroll
        for (int nf = 0; nf < 4; nf++) {
            const int col = wn * 32 + nf * 8 + rl;
            const float* d = acc[mf][nf];
            sS[row * 66 + col]           = d[0];
            sS[row * 66 + col + 1]       = d[1];
            sS[(row + 8) * 66 + col]     = d[2];
            sS[(row + 8) * 66 + col + 1] = d[3];
        }
    }
    __syncthreads();
}

// K1: nearest-centroid assignment (3-term: flip-sensitive, keep high precision)
__global__ __launch_bounds__(256, 2) void k_score_argmax() {
    extern __shared__ __align__(128) char smem[];
    float* sS = (float*)smem;
    int* hist = (int*)(smem + 128 * 66 * 4);
    const int t = threadIdx.x;
    const int b = blockIdx.y;
    const int p0 = blockIdx.x * 128;
    const __half* Ah = g_xh + ((size_t)b * HWn + p0) * Cn;
    const __half* Al = g_xl + ((size_t)b * HWn + p0) * Cn;

    sc_compute(smem, sS, Ah, Al, g_cnh, g_cnl, t);

    if (t < Kn) hist[t] = 0;
    __syncthreads();
    if (t < 128) {
        const float* row = sS + t * 66;
        float best = row[0]; int bi = 0;
#pragma unroll
        for (int k = 1; k < Kn; k++) { const float v = row[k]; if (v > best) { best = v; bi = k; } }
        g_idx[b * HWn + p0 + t] = bi;
        atomicAdd(&hist[bi], 1);
    }
    __syncthreads();
    if (t < Kn && hist[t]) atomicAdd(&g_counts[b * Kn + t], hist[t]);
}

// ---------------- K1b: per-batch exclusive prefix -----------------------------
__global__ void k_prefix() {
    const int b = blockIdx.x;
    if (threadIdx.x == 0) {
        int acc = 0;
        for (int k = 0; k < Kn; k++) {
            g_base[b * Kn + k]   = acc;
            g_cursor[b * Kn + k] = acc;
            acc += g_counts[b * Kn + k];
        }
    }
}

// ---------------- K1c: scatter pixel ids grouped by cluster ------------------
__global__ void k_scatter() {
    const int b = blockIdx.y;
    const int p = blockIdx.x * 256 + threadIdx.x;
    const int k = g_idx[b * HWn + p];
    const int pos = atomicAdd(&g_cursor[b * Kn + k], 1);
    g_order[b * HWn + pos] = p;
}

// ---------------- K2: local centroids via gather ------------------------------
__global__ void k_cl(const float* __restrict__ x) {
    __shared__ float xr[2 * HWn];
    const int b  = blockIdx.y;
    const int c0 = blockIdx.x * 2;
    const int t  = threadIdx.x;
    for (int e = t; e < 2 * HWn; e += 256)
        xr[e] = x[((size_t)b * Cn + c0 + (e >> 12)) * HWn + (e & (HWn - 1))];
    __syncthreads();
    const int warp = t >> 5, lane = t & 31;
    for (int k = warp; k < Kn; k += 8) {
        const int n   = g_counts[b * Kn + k];
        const int bas = g_base[b * Kn + k];
        float s0 = 0.f, s1 = 0.f;
        for (int i = lane; i < n; i += 32) {
            const int pix = g_order[b * HWn + bas + i];
            s0 += xr[pix];
            s1 += xr[HWn + pix];
        }
#pragma unroll
        for (int off = 16; off; off >>= 1) {
            s0 += __shfl_xor_sync(0xffffffffu, s0, off);
            s1 += __shfl_xor_sync(0xffffffffu, s1, off);
        }
        if (lane == 0) {
            const float inv = 1.f / (float)max(n, 1);
            g_cl[((size_t)b * Kn + k) * Cn + c0 + 0] = s0 * inv;
            g_cl[((size_t)b * Kn + k) * Cn + c0 + 1] = s1 * inv;
        }
    }
}

// ---------------- K3: Wcl[b,o,k] = sum_c W[o,c] * cl[b,k,c] ------------------
__global__ void k_wcl(const float* __restrict__ W) {
    __shared__ float wl[32 * 65];
    __shared__ float cls[64 * 64];
    const int b = blockIdx.y, o0 = blockIdx.x * 32, t = threadIdx.x;
    const int oL = t & 31, kset = (t >> 5) * 8;
    float acc[8];
#pragma unroll
    for (int i = 0; i < 8; i++) acc[i] = 0.f;
    for (int c0 = 0; c0 < Cn; c0 += 64) {
        for (int e = t; e < 2048; e += 256) {
            const int oi = e >> 6, ci = e & 63;
            wl[oi * 65 + ci] = W[(size_t)(o0 + oi) * Cn + c0 + ci];
        }
        for (int e = t; e < 4096; e += 256) {
            const int ki = e >> 6, ci = e & 63;
            cls[ki * 64 + ci] = g_cl[((size_t)b * Kn + ki) * Cn + c0 + ci];
        }
        __syncthreads();
        for (int ci = 0; ci < 64; ci++) {
            const float wv = wl[oL * 65 + ci];
#pragma unroll
            for (int kk = 0; kk < 8; kk++)
                acc[kk] = fmaf(wv, cls[(kset + kk) * 64 + ci], acc[kk]);
        }
        __syncthreads();
    }
#pragma unroll
    for (int kk = 0; kk < 8; kk++)
        g_wcl[((size_t)b * Cn + o0 + oL) * Kn + kset + kk] = acc[kk];
}

// ---------------- K4: calibration weight, direct (warp per pixel) -------------
// w_p = exp(-||cl[idx_p] - x_p||^2 / C); x reconstructed exactly from hi+lo.
__global__ __launch_bounds__(256) void k_wmap2() {
    const int warp = threadIdx.x >> 5, lane = threadIdx.x & 31;
    const int gp = blockIdx.x * 8 + warp;            // over Bn*HWn
    const int b = gp >> 12;
    const int k = g_idx[gp];
    const float4* cl4 = (const float4*)(g_cl + ((size_t)b * Kn + k) * Cn);
    const __half2* xh2 = (const __half2*)(g_xh + (size_t)gp * Cn);
    const __half2* xl2 = (const __half2*)(g_xl + (size_t)gp * Cn);
    float acc = 0.f;
#pragma unroll 4
    for (int j = lane; j < Cn / 4; j += 32) {
        const float4 c4 = cl4[j];
        const float2 h0 = __half22float2(xh2[2 * j]);
        const float2 h1 = __half22float2(xh2[2 * j + 1]);
        const float2 l0 = __half22float2(xl2[2 * j]);
        const float2 l1 = __half22float2(xl2[2 * j + 1]);
        const float d0 = c4.x - (h0.x + l0.x);
        const float d1 = c4.y - (h0.y + l0.y);
        const float d2 = c4.z - (h1.x + l1.x);
        const float d3 = c4.w - (h1.y + l1.y);
        acc = fmaf(d0, d0, acc);
        acc = fmaf(d1, d1, acc);
        acc = fmaf(d2, d2, acc);
        acc = fmaf(d3, d3, acc);
    }
#pragma unroll
    for (int off = 16; off; off >>= 1) acc += __shfl_xor_sync(0xffffffffu, acc, off);
    if (lane == 0) g_wmap[gp] = expf(-acc * (1.f / 1024.f));
}

// ---------------- K5a: W -> fp16 hi ------------------------------------------
__global__ void k_splitW(const float* __restrict__ W) {
    const int i = (blockIdx.x * 256 + threadIdx.x) * 2;
    const float2 v = *(const float2*)(W + i);
    __half2 hh; hh.x = __float2half_rn(v.x); hh.y = __float2half_rn(v.y);
    *(__half2*)(g_wh + i) = hh;
}

// ---------------- K5b: transpose + split x into fp16 hi/lo [b][p][c] ----------
__global__ void k_splitX(const float* __restrict__ x) {
    __shared__ float tile[32][65];   // [pj][ci]
    const int b = blockIdx.z, p0 = blockIdx.x * 32, c0 = blockIdx.y * 64;
    const int t = threadIdx.x;
    for (int e = t; e < 2048; e += 256) {
        const int ci = e >> 5, pj = e & 31;
        tile[pj][ci] = x[((size_t)b * Cn + c0 + ci) * HWn + p0 + pj];
    }
    __syncthreads();
    for (int e = t; e < 1024; e += 256) {
        const int pj = e >> 5, c2 = (e & 31) * 2;
        const float v0 = tile[pj][c2], v1 = tile[pj][c2 + 1];
        const __half h0 = __float2half_rn(v0), h1 = __float2half_rn(v1);
        __half2 hh; hh.x = h0; hh.y = h1;
        __half2 ll;
        ll.x = __float2half_rn(v0 - __half2float(h0));
        ll.y = __float2half_rn(v1 - __half2float(h1));
        const size_t dst = ((size_t)b * HWn + p0 + pj) * Cn + c0 + c2;
        *(__half2*)(g_xh + dst) = hh;
        *(__half2*)(g_xl + dst) = ll;
    }
}

// ---------------- K6: single-term fp16 HMMA GEMM, 3-stage pipe ----------------
// D[128 o, 128 p] = Wh[o,c] * Xh[p,c]  (dropped Wl.X and Wh.Xl: ~3.1e-4 rel)
#define A_T     10240                // Wh tile
#define B_T     10240                // Xh tile
#define STAGE_B (A_T + B_T)          // 20480
#define NCH     (Cn / 32)
#define GEMM_SMEM (3 * STAGE_B)      // 61440

__device__ __forceinline__ void load_chunk(uint32_t base, int b, int o0, int p0,
                                           int k0, int t) {
#pragma unroll
    for (int e = t; e < 512; e += 256) {
        const int row = e >> 2, g = e & 3;
        const uint32_t d = base + row * (PT * 2) + g * 16;
        cpa16(d,       g_wh + (size_t)(o0 + row) * Cn + k0 + g * 8);
        cpa16(d + A_T, g_xh + ((size_t)b * HWn + p0 + row) * Cn + k0 + g * 8);
    }
}

__global__ __launch_bounds__(256, 2) void k_gemm_mma(const float* __restrict__ bias,
                                                     float* __restrict__ out) {
    extern __shared__ __align__(128) char smem[];
    const uint32_t sbase = smem_u32(smem);
    const int t = threadIdx.x;
    const int wid = t >> 5, lane = t & 31;
    const int wm = wid >> 2, wn = wid & 3;      // warp tile: 64(o) x 32(p)
    const int b  = blockIdx.z;
    const int o0 = blockIdx.y * 128;
    const int p0 = blockIdx.x * 128;

    const int alr = lane & 15, alc = (lane >> 4) << 3;
    const uint32_t a_lane = (uint32_t)(((wm * 64 + alr) * PT + alc) * 2);
    const int brow = ((lane >> 4) << 3) + (lane & 7);
    const int bkc  = ((lane >> 3) & 1) << 3;
    const uint32_t b_lane = (uint32_t)(((wn * 32 + brow) * PT + bkc) * 2);

    float acc[4][4][4];
#pragma unroll
    for (int i = 0; i < 4; i++)
#pragma unroll
        for (int j = 0; j < 4; j++)
#pragma unroll
            for (int q = 0; q < 4; q++) acc[i][j][q] = 0.f;

    load_chunk(sbase,               b, o0, p0, 0,  t);  CP_COMMIT();
    load_chunk(sbase + STAGE_B,     b, o0, p0, 32, t);  CP_COMMIT();
    load_chunk(sbase + 2 * STAGE_B, b, o0, p0, 64, t);  CP_COMMIT();

    int stg = 0;
    for (int c = 0; c < NCH; c++) {
        CP_WAIT2();
        __syncthreads();
        const uint32_t st = sbase + stg * STAGE_B;
#pragma unroll
        for (int ks = 0; ks < 2; ks++) {
            uint32_t bh[8];
            ldsm_x4(bh + 0, st + A_T + b_lane + ks * 32);
            ldsm_x4(bh + 4, st + A_T + b_lane + 16 * PT * 2 + ks * 32);
#pragma unroll
            for (int mf = 0; mf < 4; mf++) {
                uint32_t ah[4];
                ldsm_x4(ah, st + a_lane + mf * 16 * PT * 2 + ks * 32);
#pragma unroll
                for (int nf = 0; nf < 4; nf++)
                    mma16816(acc[mf][nf], ah, &bh[nf * 2]);
            }
        }
        __syncthreads();
        if (c + 3 < NCH)
            load_chunk(sbase + stg * STAGE_B, b, o0, p0, (c + 3) * 32, t);
        CP_COMMIT();
        stg = (stg == 2) ? 0 : stg + 1;
    }
    CP_WAIT0();
    __syncthreads();

    float* wcl_s  = (float*)smem;            // [128][65]
    float* bias_s = wcl_s + 128 * 65;
    float* wp_s   = bias_s + 128;
    int*   kid_s  = (int*)(wp_s + 128);
    for (int e = t; e < 128 * Kn; e += 256) {
        const int oi = e >> 6, k = e & 63;
        wcl_s[oi * 65 + k] = g_wcl[(size_t)b * Cn * Kn + (size_t)(o0 + oi) * Kn + k];
    }
    if (t < 128) {
        bias_s[t] = bias[o0 + t];
        wp_s[t]   = g_wmap[b * HWn + p0 + t];
        kid_s[t]  = g_idx[b * HWn + p0 + t];
    }
    __syncthreads();

    const int ql = lane >> 2, rl = (lane & 3) * 2;
#pragma unroll
    for (int mf = 0; mf < 4; mf++) {
        const int r0 = wm * 64 + mf * 16 + ql;
        const float bi0 = bias_s[r0], bi1 = bias_s[r0 + 8];
        const float* w0 = &wcl_s[r0 * 65];
        const float* w1 = w0 + 8 * 65;
        float* op0 = out + ((size_t)b * Cn + o0 + r0) * HWn + p0;
        float* op1 = op0 + (size_t)8 * HWn;
#pragma unroll
        for (int nf = 0; nf < 4; nf++) {
            const int cc = wn * 32 + nf * 8 + rl;
            const float wpa = wp_s[cc], wpb = wp_s[cc + 1];
            const int   ka  = kid_s[cc], kb = kid_s[cc + 1];
            const float* d = acc[mf][nf];
            float2 v0, v1;
            v0.x = fmaxf(d[0] + wpa * (w0[ka] - d[0]) + bi0, 0.f);
            v0.y = fmaxf(d[1] + wpb * (w0[kb] - d[1]) + bi0, 0.f);
            v1.x = fmaxf(d[2] + wpa * (w1[ka] - d[2]) + bi1, 0.f);
            v1.y = fmaxf(d[3] + wpb * (w1[kb] - d[3]) + bi1, 0.f);
            *(float2*)(op0 + cc) = v0;
            *(float2*)(op1 + cc) = v1;
        }
    }
}

// ---------------- launch -----------------------------------------------------
extern "C" void kernel_launch(void* const* d_in, const int* in_sizes, int n_in,
                              void* d_out, int out_size) {
    const float* x    = (const float*)d_in[0];
    const float* cent = (const float*)d_in[1];
    const float* W    = (const float*)d_in[2];
    const float* bias = (const float*)d_in[3];
    float* out = (float*)d_out;

    cudaFuncSetAttribute(k_gemm_mma, cudaFuncAttributeMaxDynamicSharedMemorySize, GEMM_SMEM);
    cudaFuncSetAttribute(k_score_argmax, cudaFuncAttributeMaxDynamicSharedMemorySize, SC_SMEM);

    k_splitW <<<Cn * Cn / 512, 256>>>(W);
    k_splitX <<<dim3(HWn / 32, Cn / 64, Bn), 256>>>(x);
    k_prep   <<<Kn, 256>>>(cent);
    k_score_argmax<<<dim3(HWn / 128, Bn), 256, SC_SMEM>>>();
    k_prefix <<<Bn, 32>>>();
    k_scatter<<<dim3(HWn / 256, Bn), 256>>>();
    k_cl     <<<dim3(Cn / 2, Bn), 256>>>(x);
    k_wcl    <<<dim3(Cn / 32, Bn), 256>>>(W);
    k_wmap2  <<<Bn * HWn / 8, 256>>>();
    k_gemm_mma<<<dim3(HWn / 128, Cn / 128, Bn), 256, GEMM_SMEM>>>(bias, out);
}

// round 13
// speedup vs baseline: 3.6759x; 1.0159x over previous
#include <cuda_runtime.h>
#include <cuda_fp16.h>
#include <cstdint>

#define Bn  8
#define Cn  1024
#define HWn 4096
#define Kn  64

// ---------------- device scratch (no allocations allowed) ----------------
__device__ int   g_idx[Bn * HWn];      // argmax cluster per pixel
__device__ int   g_counts[Bn * Kn];
__device__ int   g_base[Bn * Kn];
__device__ int   g_cursor[Bn * Kn];
__device__ int   g_order[Bn * HWn];    // pixel ids grouped by cluster (per batch)
__device__ float g_cl[Bn * Kn * Cn];   // local centroids [b][k][c]
__device__ float g_wcl[Bn * Cn * Kn];  // W @ cl^T  [b][o][k]
__device__ float g_wmap[Bn * HWn];     // calibration weight per pixel

// fp16 hi/lo split operands
__device__ __half g_wh[Cn * Cn];                       // W hi, [o][c]
__device__ __half g_xh[(size_t)Bn * HWn * Cn];         // x^T hi, [b][p][c]
__device__ __half g_xl[(size_t)Bn * HWn * Cn];         // x^T lo
__device__ __half g_cnh[Kn * Cn];                      // normalized centroids hi [k][c]
__device__ __half g_cnl[Kn * Cn];                      // normalized centroids lo

// ---------------- baseline-PTX helpers (compute_103-safe) ----------------
__device__ __forceinline__ uint32_t smem_u32(const void* p) {
    uint32_t a;
    asm("{ .reg .u64 t; cvta.to.shared.u64 t, %1; cvt.u32.u64 %0, t; }" : "=r"(a) : "l"(p));
    return a;
}
__device__ __forceinline__ void cpa16(uint32_t dst, const void* src) {
    asm volatile("cp.async.cg.shared.global [%0], [%1], 16;"
                 :: "r"(dst), "l"(__cvta_generic_to_global(src)) : "memory");
}
#define CP_COMMIT() asm volatile("cp.async.commit_group;" ::: "memory")
#define CP_WAIT1()  asm volatile("cp.async.wait_group 1;" ::: "memory")
#define CP_WAIT0()  asm volatile("cp.async.wait_group 0;" ::: "memory")

__device__ __forceinline__ void ldsm_x4(uint32_t* r, uint32_t addr) {
    asm volatile("ldmatrix.sync.aligned.m8n8.x4.shared.b16 {%0,%1,%2,%3}, [%4];"
                 : "=r"(r[0]), "=r"(r[1]), "=r"(r[2]), "=r"(r[3]) : "r"(addr));
}
__device__ __forceinline__ void mma16816(float* d, const uint32_t* a, const uint32_t* b) {
    asm volatile("mma.sync.aligned.m16n8k16.row.col.f32.f16.f16.f32 "
                 "{%0,%1,%2,%3}, {%4,%5,%6,%7}, {%8,%9}, {%0,%1,%2,%3};"
                 : "+f"(d[0]), "+f"(d[1]), "+f"(d[2]), "+f"(d[3])
                 : "r"(a[0]), "r"(a[1]), "r"(a[2]), "r"(a[3]), "r"(b[0]), "r"(b[1]));
}

// ---------------- K0: normalize centroids -> fp16 hi/lo [k][c]; zero counts ---
__global__ void k_prep(const float* __restrict__ cent) {
    const int kk = blockIdx.x;
    const int t  = threadIdx.x;
    __shared__ float red[256];
    float s = 0.f;
    for (int c = t; c < Cn; c += 256) { float v = cent[kk * Cn + c]; s = fmaf(v, v, s); }
    red[t] = s; __syncthreads();
    for (int o = 128; o; o >>= 1) { if (t < o) red[t] += red[t + o]; __syncthreads(); }
    const float scale = 1.f / fmaxf(sqrtf(red[0]), 1e-12f);
    for (int c = t; c < Cn; c += 256) {
        const float v = cent[kk * Cn + c] * scale;
        const __half h = __float2half_rn(v);
        g_cnh[kk * Cn + c] = h;
        g_cnl[kk * Cn + c] = __float2half_rn(v - __half2float(h));
    }
    if (blockIdx.x == 0 && t < 256) { g_counts[t] = 0; g_counts[256 + t] = 0; }
}

// ---------------- argmax score kernel: S[128p x 64k] via 3-term fp16 MMA ------
// 3-stage cp.async pipeline, ONE __syncthreads per k-chunk.
#define PT      40                   // SMEM pitch in fp16 elems (80 B)
#define SC_AT   (128 * PT * 2)       // 10240 B per A tile
#define SC_BT   (64 * PT * 2)        // 5120 B per B tile
#define SC_STAGE (2 * SC_AT + 2 * SC_BT)   // 30720
#define SC_SMEM  (3 * SC_STAGE)            // 92160
#define SC_NCH   (Cn / 32)

__device__ __forceinline__ void sc_load(uint32_t base,
                                        const __half* Ah, const __half* Al,
                                        const __half* Bh, const __half* Bl,
                                        int k0, int t) {
#pragma unroll
    for (int e = t; e < 512; e += 256) {
        const int row = e >> 2, g = e & 3;
        const uint32_t d = base + row * (PT * 2) + g * 16;
        const size_t s = (size_t)row * Cn + k0 + g * 8;
        cpa16(d,         Ah + s);
        cpa16(d + SC_AT, Al + s);
    }
    {
        const int row = t >> 2, g = t & 3;
        const uint32_t d = base + 2 * SC_AT + row * (PT * 2) + g * 16;
        const size_t s = (size_t)row * Cn + k0 + g * 8;
        cpa16(d,         Bh + s);
        cpa16(d + SC_BT, Bl + s);
    }
}

// S = Ah.Bh + Ah.Bl + Al.Bh  into sS[128][66]
__device__ __forceinline__ void sc_compute(char* smem, float* sS,
                                           const __half* Ah, const __half* Al,
                                           const __half* Bh, const __half* Bl,
                                           int t) {
    const uint32_t sbase = smem_u32(smem);
    const int wid = t >> 5, lane = t & 31;
    const int wm = wid >> 1, wn = wid & 1;       // warp tile 32p x 32k
    const int alr = lane & 15, alc = (lane >> 4) << 3;
    const uint32_t a_lane = (uint32_t)(((wm * 32 + alr) * PT + alc) * 2);
    const int brow = ((lane >> 4) << 3) + (lane & 7);
    const int bkc  = ((lane >> 3) & 1) << 3;
    const uint32_t b_lane = (uint32_t)(((wn * 32 + brow) * PT + bkc) * 2);

    float acc[2][4][4];
#pragma unroll
    for (int i = 0; i < 2; i++)
#pragma unroll
        for (int j = 0; j < 4; j++)
#pragma unroll
            for (int q = 0; q < 4; q++) acc[i][j][q] = 0.f;

    sc_load(sbase,            Ah, Al, Bh, Bl, 0,  t);  CP_COMMIT();
    sc_load(sbase + SC_STAGE, Ah, Al, Bh, Bl, 32, t);  CP_COMMIT();

    for (int c = 0; c < SC_NCH; c++) {
        CP_WAIT1();
        __syncthreads();
        // refill stage (c+2)%3: finished compute at iter c-1, safe after sync
        if (c + 2 < SC_NCH)
            sc_load(sbase + ((c + 2) % 3) * SC_STAGE, Ah, Al, Bh, Bl, (c + 2) * 32, t);
        CP_COMMIT();
        const uint32_t st = sbase + (c % 3) * SC_STAGE;
#pragma unroll
        for (int ks = 0; ks < 2; ks++) {
            uint32_t bh[8], bl[8];
            ldsm_x4(bh + 0, st + 2 * SC_AT + b_lane + ks * 32);
            ldsm_x4(bh + 4, st + 2 * SC_AT + b_lane + 16 * PT * 2 + ks * 32);
            ldsm_x4(bl + 0, st + 2 * SC_AT + SC_BT + b_lane + ks * 32);
            ldsm_x4(bl + 4, st + 2 * SC_AT + SC_BT + b_lane + 16 * PT * 2 + ks * 32);
#pragma unroll
            for (int mf = 0; mf < 2; mf++) {
                uint32_t ah[4], al[4];
                ldsm_x4(ah, st + a_lane + mf * 16 * PT * 2 + ks * 32);
                ldsm_x4(al, st + SC_AT + a_lane + mf * 16 * PT * 2 + ks * 32);
#pragma unroll
                for (int nf = 0; nf < 4; nf++) {
                    mma16816(acc[mf][nf], ah, &bh[nf * 2]);
                    mma16816(acc[mf][nf], ah, &bl[nf * 2]);
                    mma16816(acc[mf][nf], al, &bh[nf * 2]);
                }
            }
        }
    }
    CP_WAIT0();
    __syncthreads();

    const int ql = lane >> 2, rl = (lane & 3) * 2;
#pragma unroll
    for (int mf = 0; mf < 2; mf++) {
        const int row = wm * 32 + mf * 16 + ql;
#pragma unroll
        for (int nf = 0; nf < 4; nf++) {
            const int col = wn * 32 + nf * 8 + rl;
            const float* d = acc[mf][nf];
            sS[row * 66 + col]           = d[0];
            sS[row * 66 + col + 1]       = d[1];
            sS[(row + 8) * 66 + col]     = d[2];
            sS[(row + 8) * 66 + col + 1] = d[3];
        }
    }
    __syncthreads();
}

// K1: nearest-centroid assignment (3-term: flip-sensitive, keep high precision)
__global__ __launch_bounds__(256, 2) void k_score_argmax() {
    extern __shared__ __align__(128) char smem[];
    float* sS = (float*)smem;
    int* hist = (int*)(smem + 128 * 66 * 4);
    const int t = threadIdx.x;
    const int b = blockIdx.y;
    const int p0 = blockIdx.x * 128;
    const __half* Ah = g_xh + ((size_t)b * HWn + p0) * Cn;
    const __half* Al = g_xl + ((size_t)b * HWn + p0) * Cn;

    sc_compute(smem, sS, Ah, Al, g_cnh, g_cnl, t);

    if (t < Kn) hist[t] = 0;
    __syncthreads();
    if (t < 128) {
        const float* row = sS + t * 66;
        float best = row[0]; int bi = 0;
#pragma unroll
        for (int k = 1; k < Kn; k++) { const float v = row[k]; if (v > best) { best = v; bi = k; } }
        g_idx[b * HWn + p0 + t] = bi;
        atomicAdd(&hist[bi], 1);
    }
    __syncthreads();
    if (t < Kn && hist[t]) atomicAdd(&g_counts[b * Kn + t], hist[t]);
}

// ---------------- K1b: per-batch exclusive prefix -----------------------------
__global__ void k_prefix() {
    const int b = blockIdx.x;
    if (threadIdx.x == 0) {
        int acc = 0;
        for (int k = 0; k < Kn; k++) {
            g_base[b * Kn + k]   = acc;
            g_cursor[b * Kn + k] = acc;
            acc += g_counts[b * Kn + k];
        }
    }
}

// ---------------- K1c: scatter pixel ids grouped by cluster ------------------
__global__ void k_scatter() {
    const int b = blockIdx.y;
    const int p = blockIdx.x * 256 + threadIdx.x;
    const int k = g_idx[b * HWn + p];
    const int pos = atomicAdd(&g_cursor[b * Kn + k], 1);
    g_order[b * HWn + pos] = p;
}

// ---------------- K2: local centroids via gather ------------------------------
__global__ void k_cl(const float* __restrict__ x) {
    __shared__ float xr[2 * HWn];
    const int b  = blockIdx.y;
    const int c0 = blockIdx.x * 2;
    const int t  = threadIdx.x;
    for (int e = t; e < 2 * HWn; e += 256)
        xr[e] = x[((size_t)b * Cn + c0 + (e >> 12)) * HWn + (e & (HWn - 1))];
    __syncthreads();
    const int warp = t >> 5, lane = t & 31;
    for (int k = warp; k < Kn; k += 8) {
        const int n   = g_counts[b * Kn + k];
        const int bas = g_base[b * Kn + k];
        float s0 = 0.f, s1 = 0.f;
        for (int i = lane; i < n; i += 32) {
            const int pix = g_order[b * HWn + bas + i];
            s0 += xr[pix];
            s1 += xr[HWn + pix];
        }
#pragma unroll
        for (int off = 16; off; off >>= 1) {
            s0 += __shfl_xor_sync(0xffffffffu, s0, off);
            s1 += __shfl_xor_sync(0xffffffffu, s1, off);
        }
        if (lane == 0) {
            const float inv = 1.f / (float)max(n, 1);
            g_cl[((size_t)b * Kn + k) * Cn + c0 + 0] = s0 * inv;
            g_cl[((size_t)b * Kn + k) * Cn + c0 + 1] = s1 * inv;
        }
    }
}

// ---------------- K3: Wcl[b,o,k] = sum_c W[o,c] * cl[b,k,c] ------------------
__global__ void k_wcl(const float* __restrict__ W) {
    __shared__ float wl[32 * 65];
    __shared__ float cls[64 * 64];
    const int b = blockIdx.y, o0 = blockIdx.x * 32, t = threadIdx.x;
    const int oL = t & 31, kset = (t >> 5) * 8;
    float acc[8];
#pragma unroll
    for (int i = 0; i < 8; i++) acc[i] = 0.f;
    for (int c0 = 0; c0 < Cn; c0 += 64) {
        for (int e = t; e < 2048; e += 256) {
            const int oi = e >> 6, ci = e & 63;
            wl[oi * 65 + ci] = W[(size_t)(o0 + oi) * Cn + c0 + ci];
        }
        for (int e = t; e < 4096; e += 256) {
            const int ki = e >> 6, ci = e & 63;
            cls[ki * 64 + ci] = g_cl[((size_t)b * Kn + ki) * Cn + c0 + ci];
        }
        __syncthreads();
        for (int ci = 0; ci < 64; ci++) {
            const float wv = wl[oL * 65 + ci];
#pragma unroll
            for (int kk = 0; kk < 8; kk++)
                acc[kk] = fmaf(wv, cls[(kset + kk) * 64 + ci], acc[kk]);
        }
        __syncthreads();
    }
#pragma unroll
    for (int kk = 0; kk < 8; kk++)
        g_wcl[((size_t)b * Cn + o0 + oL) * Kn + kset + kk] = acc[kk];
}

// ---------------- K4: calibration weight, direct (warp per pixel) -------------
__global__ __launch_bounds__(256) void k_wmap2() {
    const int warp = threadIdx.x >> 5, lane = threadIdx.x & 31;
    const int gp = blockIdx.x * 8 + warp;            // over Bn*HWn
    const int b = gp >> 12;
    const int k = g_idx[gp];
    const float4* cl4 = (const float4*)(g_cl + ((size_t)b * Kn + k) * Cn);
    const __half2* xh2 = (const __half2*)(g_xh + (size_t)gp * Cn);
    const __half2* xl2 = (const __half2*)(g_xl + (size_t)gp * Cn);
    float acc = 0.f;
#pragma unroll 4
    for (int j = lane; j < Cn / 4; j += 32) {
        const float4 c4 = cl4[j];
        const float2 h0 = __half22float2(xh2[2 * j]);
        const float2 h1 = __half22float2(xh2[2 * j + 1]);
        const float2 l0 = __half22float2(xl2[2 * j]);
        const float2 l1 = __half22float2(xl2[2 * j + 1]);
        const float d0 = c4.x - (h0.x + l0.x);
        const float d1 = c4.y - (h0.y + l0.y);
        const float d2 = c4.z - (h1.x + l1.x);
        const float d3 = c4.w - (h1.y + l1.y);
        acc = fmaf(d0, d0, acc);
        acc = fmaf(d1, d1, acc);
        acc = fmaf(d2, d2, acc);
        acc = fmaf(d3, d3, acc);
    }
#pragma unroll
    for (int off = 16; off; off >>= 1) acc += __shfl_xor_sync(0xffffffffu, acc, off);
    if (lane == 0) g_wmap[gp] = expf(-acc * (1.f / 1024.f));
}

// ---------------- K5a: W -> fp16 hi ------------------------------------------
__global__ void k_splitW(const float* __restrict__ W) {
    const int i = (blockIdx.x * 256 + threadIdx.x) * 2;
    const float2 v = *(const float2*)(W + i);
    __half2 hh; hh.x = __float2half_rn(v.x); hh.y = __float2half_rn(v.y);
    *(__half2*)(g_wh + i) = hh;
}

// ---------------- K5b: transpose + split x into fp16 hi/lo [b][p][c] ----------
__global__ void k_splitX(const float* __restrict__ x) {
    __shared__ float tile[32][65];   // [pj][ci]
    const int b = blockIdx.z, p0 = blockIdx.x * 32, c0 = blockIdx.y * 64;
    const int t = threadIdx.x;
    for (int e = t; e < 2048; e += 256) {
        const int ci = e >> 5, pj = e & 31;
        tile[pj][ci] = x[((size_t)b * Cn + c0 + ci) * HWn + p0 + pj];
    }
    __syncthreads();
    for (int e = t; e < 1024; e += 256) {
        const int pj = e >> 5, c2 = (e & 31) * 2;
        const float v0 = tile[pj][c2], v1 = tile[pj][c2 + 1];
        const __half h0 = __float2half_rn(v0), h1 = __float2half_rn(v1);
        __half2 hh; hh.x = h0; hh.y = h1;
        __half2 ll;
        ll.x = __float2half_rn(v0 - __half2float(h0));
        ll.y = __float2half_rn(v1 - __half2float(h1));
        const size_t dst = ((size_t)b * HWn + p0 + pj) * Cn + c0 + c2;
        *(__half2*)(g_xh + dst) = hh;
        *(__half2*)(g_xl + dst) = ll;
    }
}

// ---------------- K6: single-term fp16 HMMA GEMM ------------------------------
// D[128 o, 128 p] = Wh[o,c] * Xh[p,c].
// k-chunk 64, 3-stage cp.async pipeline, ONE __syncthreads per chunk.
#define GPT     72                   // pitch in fp16 elems (144 B; banks 0,4,..,28)
#define GA_T    (128 * GPT * 2)      // 18432 B per operand tile
#define GSTAGE  (2 * GA_T)           // 36864
#define GNCH    (Cn / 64)            // 16
#define GEMM_SMEM (3 * GSTAGE)       // 110592

__device__ __forceinline__ void load_chunk(uint32_t base, int b, int o0, int p0,
                                           int k0, int t) {
#pragma unroll
    for (int e = t; e < 1024; e += 256) {
        const int row = e >> 3, g = e & 7;
        const uint32_t d = base + row * (GPT * 2) + g * 16;
        cpa16(d,        g_wh + (size_t)(o0 + row) * Cn + k0 + g * 8);
        cpa16(d + GA_T, g_xh + ((size_t)b * HWn + p0 + row) * Cn + k0 + g * 8);
    }
}

__global__ __launch_bounds__(256, 2) void k_gemm_mma(const float* __restrict__ bias,
                                                     float* __restrict__ out) {
    extern __shared__ __align__(128) char smem[];
    const uint32_t sbase = smem_u32(smem);
    const int t = threadIdx.x;
    const int wid = t >> 5, lane = t & 31;
    const int wm = wid >> 2, wn = wid & 3;      // warp tile: 64(o) x 32(p)
    const int b  = blockIdx.z;
    const int o0 = blockIdx.y * 128;
    const int p0 = blockIdx.x * 128;

    const int alr = lane & 15, alc = (lane >> 4) << 3;
    const uint32_t a_lane = (uint32_t)(((wm * 64 + alr) * GPT + alc) * 2);
    const int brow = ((lane >> 4) << 3) + (lane & 7);
    const int bkc  = ((lane >> 3) & 1) << 3;
    const uint32_t b_lane = (uint32_t)(((wn * 32 + brow) * GPT + bkc) * 2);

    float acc[4][4][4];
#pragma unroll
    for (int i = 0; i < 4; i++)
#pragma unroll
        for (int j = 0; j < 4; j++)
#pragma unroll
            for (int q = 0; q < 4; q++) acc[i][j][q] = 0.f;

    load_chunk(sbase,          b, o0, p0, 0,  t);  CP_COMMIT();
    load_chunk(sbase + GSTAGE, b, o0, p0, 64, t);  CP_COMMIT();

    for (int c = 0; c < GNCH; c++) {
        CP_WAIT1();
        __syncthreads();
        // refill stage (c+2)%3: computed at iter c-1, safe after this sync
        if (c + 2 < GNCH)
            load_chunk(sbase + ((c + 2) % 3) * GSTAGE, b, o0, p0, (c + 2) * 64, t);
        CP_COMMIT();
        const uint32_t st = sbase + (c % 3) * GSTAGE;
#pragma unroll
        for (int ks = 0; ks < 4; ks++) {
            uint32_t bh[8];
            ldsm_x4(bh + 0, st + GA_T + b_lane + ks * 32);
            ldsm_x4(bh + 4, st + GA_T + b_lane + 16 * GPT * 2 + ks * 32);
#pragma unroll
            for (int mf = 0; mf < 4; mf++) {
                uint32_t ah[4];
                ldsm_x4(ah, st + a_lane + mf * 16 * GPT * 2 + ks * 32);
#pragma unroll
                for (int nf = 0; nf < 4; nf++)
                    mma16816(acc[mf][nf], ah, &bh[nf * 2]);
            }
        }
    }
    CP_WAIT0();
    __syncthreads();

    float* wcl_s  = (float*)smem;            // [128][65]
    float* bias_s = wcl_s + 128 * 65;
    float* wp_s   = bias_s + 128;
    int*   kid_s  = (int*)(wp_s + 128);
    for (int e = t; e < 128 * Kn; e += 256) {
        const int oi = e >> 6, k = e & 63;
        wcl_s[oi * 65 + k] = g_wcl[(size_t)b * Cn * Kn + (size_t)(o0 + oi) * Kn + k];
    }
    if (t < 128) {
        bias_s[t] = bias[o0 + t];
        wp_s[t]   = g_wmap[b * HWn + p0 + t];
        kid_s[t]  = g_idx[b * HWn + p0 + t];
    }
    __syncthreads();

    const int ql = lane >> 2, rl = (lane & 3) * 2;
#pragma unroll
    for (int mf = 0; mf < 4; mf++) {
        const int r0 = wm * 64 + mf * 16 + ql;
        const float bi0 = bias_s[r0], bi1 = bias_s[r0 + 8];
        const float* w0 = &wcl_s[r0 * 65];
        const float* w1 = w0 + 8 * 65;
        float* op0 = out + ((size_t)b * Cn + o0 + r0) * HWn + p0;
        float* op1 = op0 + (size_t)8 * HWn;
#pragma unroll
        for (int nf = 0; nf < 4; nf++) {
            const int cc = wn * 32 + nf * 8 + rl;
            const float wpa = wp_s[cc], wpb = wp_s[cc + 1];
            const int   ka  = kid_s[cc], kb = kid_s[cc + 1];
            const float* d = acc[mf][nf];
            float2 v0, v1;
            v0.x = fmaxf(d[0] + wpa * (w0[ka] - d[0]) + bi0, 0.f);
            v0.y = fmaxf(d[1] + wpb * (w0[kb] - d[1]) + bi0, 0.f);
            v1.x = fmaxf(d[2] + wpa * (w1[ka] - d[2]) + bi1, 0.f);
            v1.y = fmaxf(d[3] + wpb * (w1[kb] - d[3]) + bi1, 0.f);
            *(float2*)(op0 + cc) = v0;
            *(float2*)(op1 + cc) = v1;
        }
    }
}

// ---------------- launch -----------------------------------------------------
extern "C" void kernel_launch(void* const* d_in, const int* in_sizes, int n_in,
                              void* d_out, int out_size) {
    const float* x    = (const float*)d_in[0];
    const float* cent = (const float*)d_in[1];
    const float* W    = (const float*)d_in[2];
    const float* bias = (const float*)d_in[3];
    float* out = (float*)d_out;

    cudaFuncSetAttribute(k_gemm_mma, cudaFuncAttributeMaxDynamicSharedMemorySize, GEMM_SMEM);
    cudaFuncSetAttribute(k_score_argmax, cudaFuncAttributeMaxDynamicSharedMemorySize, SC_SMEM);

    k_splitW <<<Cn * Cn / 512, 256>>>(W);
    k_splitX <<<dim3(HWn / 32, Cn / 64, Bn), 256>>>(x);
    k_prep   <<<Kn, 256>>>(cent);
    k_score_argmax<<<dim3(HWn / 128, Bn), 256, SC_SMEM>>>();
    k_prefix <<<Bn, 32>>>();
    k_scatter<<<dim3(HWn / 256, Bn), 256>>>();
    k_cl     <<<dim3(Cn / 2, Bn), 256>>>(x);
    k_wcl    <<<dim3(Cn / 32, Bn), 256>>>(W);
    k_wmap2  <<<Bn * HWn / 8, 256>>>();
    k_gemm_mma<<<dim3(HWn / 128, Cn / 128, Bn), 256, GEMM_SMEM>>>(bias, out);
}